// round 6
// baseline (speedup 1.0000x reference)
#include <cuda_runtime.h>
#include <math.h>

#define Bdim 4
#define Sdim 2048
#define Edim 1024
#define Hdim 16
#define Dh   64
#define FFd  4096
#define NTOK (Bdim*Sdim)      // 8192
#define E3   (3*Edim)         // 3072
#define WIN  128              // half window
#define LNEPS 1e-5f

// ---------------- scratch (static device memory, no allocs) ----------------
__device__ float g_h   [NTOK*(size_t)Edim];   // ln1 out / ln2 out (reused)
__device__ float g_qkv [NTOK*(size_t)E3];     // qkv
__device__ float g_attn[NTOK*(size_t)Edim];   // attention out (B,S,E)
__device__ float g_x1  [NTOK*(size_t)Edim];   // residual 1
__device__ float g_h2  [NTOK*(size_t)Edim];   // ln2 out
__device__ float g_gate[NTOK*(size_t)FFd];    // gate -> gelu(gate)*val
__device__ float g_val [NTOK*(size_t)FFd];    // (unused scratch, kept for safety)

// ---------------- layernorm: one block (256 thr) per token ----------------
__global__ void ln_kernel(const float* __restrict__ x,
                          const float* __restrict__ gamma,
                          const float* __restrict__ beta,
                          float* __restrict__ out) {
    int n = blockIdx.x;
    int tid = threadIdx.x;
    const float* row = x + (size_t)n * Edim;
    float* orow = out + (size_t)n * Edim;

    float v[4];
    float s = 0.f;
#pragma unroll
    for (int i = 0; i < 4; i++) { v[i] = row[tid + 256 * i]; s += v[i]; }

    __shared__ float sh[8];
    int lane = tid & 31, warp = tid >> 5;
#pragma unroll
    for (int o = 16; o; o >>= 1) s += __shfl_xor_sync(0xffffffffu, s, o);
    if (lane == 0) sh[warp] = s;
    __syncthreads();
    if (tid < 8) {
        float t = sh[tid];
#pragma unroll
        for (int o = 4; o; o >>= 1) t += __shfl_xor_sync(0xffu, t, o);
        if (tid == 0) sh[0] = t;
    }
    __syncthreads();
    float mu = sh[0] * (1.f / Edim);
    __syncthreads();

    float s2 = 0.f;
#pragma unroll
    for (int i = 0; i < 4; i++) { float d = v[i] - mu; s2 += d * d; }
#pragma unroll
    for (int o = 16; o; o >>= 1) s2 += __shfl_xor_sync(0xffffffffu, s2, o);
    if (lane == 0) sh[warp] = s2;
    __syncthreads();
    if (tid < 8) {
        float t = sh[tid];
#pragma unroll
        for (int o = 4; o; o >>= 1) t += __shfl_xor_sync(0xffu, t, o);
        if (tid == 0) sh[0] = t;
    }
    __syncthreads();
    float var = sh[0] * (1.f / Edim);
    float r = rsqrtf(var + LNEPS);

#pragma unroll
    for (int i = 0; i < 4; i++) {
        int c = tid + 256 * i;
        orow[c] = (v[i] - mu) * r * gamma[c] + beta[c];
    }
}

// ---------------- GEMM: C[M,N] = A[M,K] @ W[K,N] + bias, epilogues --------
// EPI: 0 = bias only; 1 = bias + res add; 2 = gelu(gate)*(acc+bias)
// 128x128 block tile, BK=8, 256 threads, 8x8 per-thread micro-tile.
template <int EPI>
__global__ void gemm_kernel(const float* __restrict__ A,
                            const float* __restrict__ W,
                            const float* __restrict__ bias,
                            const float* __restrict__ aux,  // res (EPI=1) or gate (EPI=2)
                            float* __restrict__ C,
                            int M, int N, int K) {
    __shared__ float As[8][128];
    __shared__ float Bs[8][128];

    int bm = blockIdx.y * 128;
    int bn = blockIdx.x * 128;
    int tid = threadIdx.x;
    int tr = tid >> 4;         // 0..15
    int tc = tid & 15;         // 0..15

    const float* Ab = A + (size_t)bm * K;
    const float* Wb = W + bn;

    int arow = tid >> 1;               // 0..127
    int acol = (tid & 1) * 4;          // 0 or 4
    int brow = tid >> 5;               // 0..7
    int bcol = (tid & 31) * 4;         // 0..124

    float acc[8][8];
#pragma unroll
    for (int i = 0; i < 8; i++)
#pragma unroll
        for (int j = 0; j < 8; j++) acc[i][j] = 0.f;

    for (int k0 = 0; k0 < K; k0 += 8) {
        float4 a = *(const float4*)(Ab + (size_t)arow * K + k0 + acol);
        As[acol + 0][arow] = a.x;
        As[acol + 1][arow] = a.y;
        As[acol + 2][arow] = a.z;
        As[acol + 3][arow] = a.w;
        float4 b = *(const float4*)(Wb + (size_t)(k0 + brow) * N + bcol);
        *(float4*)&Bs[brow][bcol] = b;
        __syncthreads();

#pragma unroll
        for (int kk = 0; kk < 8; kk++) {
            float4 a0 = *(const float4*)&As[kk][tr * 8];
            float4 a1 = *(const float4*)&As[kk][tr * 8 + 4];
            float4 b0 = *(const float4*)&Bs[kk][tc * 8];
            float4 b1 = *(const float4*)&Bs[kk][tc * 8 + 4];
            float ar[8] = {a0.x, a0.y, a0.z, a0.w, a1.x, a1.y, a1.z, a1.w};
            float br[8] = {b0.x, b0.y, b0.z, b0.w, b1.x, b1.y, b1.z, b1.w};
#pragma unroll
            for (int i = 0; i < 8; i++)
#pragma unroll
                for (int j = 0; j < 8; j++) acc[i][j] += ar[i] * br[j];
        }
        __syncthreads();
    }

#pragma unroll
    for (int i = 0; i < 8; i++) {
        int r = bm + tr * 8 + i;
#pragma unroll
        for (int j = 0; j < 8; j += 4) {
            int c = bn + tc * 8 + j;
            float4 bia = *(const float4*)(bias + c);
            float4 o;
            o.x = acc[i][j + 0] + bia.x;
            o.y = acc[i][j + 1] + bia.y;
            o.z = acc[i][j + 2] + bia.z;
            o.w = acc[i][j + 3] + bia.w;
            if (EPI == 1) {
                float4 rr = *(const float4*)(aux + (size_t)r * N + c);
                o.x += rr.x; o.y += rr.y; o.z += rr.z; o.w += rr.w;
            }
            if (EPI == 2) {
                float4 gg = *(const float4*)(aux + (size_t)r * N + c);
                float k = 0.7071067811865476f;
                o.x *= 0.5f * gg.x * (1.f + erff(gg.x * k));
                o.y *= 0.5f * gg.y * (1.f + erff(gg.y * k));
                o.z *= 0.5f * gg.z * (1.f + erff(gg.z * k));
                o.w *= 0.5f * gg.w * (1.f + erff(gg.w * k));
            }
            *(float4*)(C + (size_t)r * N + c) = o;
        }
    }
}

// ---------------- RoPE: in-place on q,k parts of qkv -----------------------
// grid = NTOK blocks, block = 512 threads: h = tid/32, j = tid%32
__global__ void rope_kernel(float* __restrict__ qkv) {
    int n = blockIdx.x;
    int s = n & (Sdim - 1);
    int tid = threadIdx.x;
    int h = tid >> 5;
    int j = tid & 31;
    float inv = expf(-(float)(2 * j) * (1.f / 64.f) * 9.210340371976184f);
    float ang = (float)s * inv;
    float c, sn;
    sincosf(ang, &sn, &c);
#pragma unroll
    for (int cc = 0; cc < 2; cc++) {
        float* p = qkv + (size_t)n * E3 + cc * Edim + h * Dh;
        float x1 = p[j];
        float x2 = p[j + 32];
        p[j]      = x1 * c - x2 * sn;
        p[j + 32] = x2 * c + x1 * sn;
    }
}

// ---------------- sliding-window attention: one block per (b,h,q) ----------
__global__ void attn_kernel(const float* __restrict__ qkv,
                            float* __restrict__ out) {
    int q  = blockIdx.x & (Sdim - 1);
    int bh = blockIdx.x >> 11;      // log2(Sdim)=11
    int h  = bh & (Hdim - 1);
    int b  = bh >> 4;               // log2(Hdim)=4
    int tid = threadIdx.x;          // 256
    int lane = tid & 31, warp = tid >> 5;

    int ks = q - WIN; if (ks < 0) ks = 0;
    int ke = q + WIN; if (ke > Sdim - 1) ke = Sdim - 1;
    int nk = ke - ks + 1;           // <= 257

    __shared__ float qv[64];
    __shared__ float sc[257];
    __shared__ float red[8];

    const float* qp = qkv + ((size_t)(b * Sdim + q)) * E3 + h * Dh;
    if (tid < 64) qv[tid] = qp[tid];
    __syncthreads();

    for (int kk = warp; kk < nk; kk += 8) {
        const float* kp = qkv + ((size_t)(b * Sdim + ks + kk)) * E3 + Edim + h * Dh;
        float p = qv[2 * lane] * kp[2 * lane] + qv[2 * lane + 1] * kp[2 * lane + 1];
#pragma unroll
        for (int o = 16; o; o >>= 1) p += __shfl_xor_sync(0xffffffffu, p, o);
        if (lane == 0) sc[kk] = p * 0.125f;   // 1/sqrt(64)
    }
    __syncthreads();

    float m = -1e30f;
    for (int i = tid; i < nk; i += 256) m = fmaxf(m, sc[i]);
#pragma unroll
    for (int o = 16; o; o >>= 1) m = fmaxf(m, __shfl_xor_sync(0xffffffffu, m, o));
    if (lane == 0) red[warp] = m;
    __syncthreads();
    if (tid < 8) {
        float t = red[tid];
#pragma unroll
        for (int o = 4; o; o >>= 1) t = fmaxf(t, __shfl_xor_sync(0xffu, t, o));
        if (tid == 0) red[0] = t;
    }
    __syncthreads();
    m = red[0];
    __syncthreads();

    float s = 0.f;
    for (int i = tid; i < nk; i += 256) { float e = expf(sc[i] - m); sc[i] = e; s += e; }
#pragma unroll
    for (int o = 16; o; o >>= 1) s += __shfl_xor_sync(0xffffffffu, s, o);
    if (lane == 0) red[warp] = s;
    __syncthreads();
    if (tid < 8) {
        float t = red[tid];
#pragma unroll
        for (int o = 4; o; o >>= 1) t += __shfl_xor_sync(0xffu, t, o);
        if (tid == 0) red[0] = t;
    }
    __syncthreads();
    float invsum = 1.f / red[0];

    if (tid < 64) {
        float acc = 0.f;
        const float* vp = qkv + ((size_t)(b * Sdim + ks)) * E3 + 2 * Edim + h * Dh + tid;
        for (int kk = 0; kk < nk; kk++) acc += sc[kk] * vp[(size_t)kk * E3];
        out[((size_t)(b * Sdim + q)) * Edim + h * Dh + tid] = acc * invsum;
    }
}

// ---------------- launch ---------------------------------------------------
extern "C" void kernel_launch(void* const* d_in, const int* in_sizes, int n_in,
                              void* d_out, int out_size) {
    const float* src    = (const float*)d_in[0];
    const float* Wqkv   = (const float*)d_in[1];
    const float* bqkv   = (const float*)d_in[2];
    const float* Wout   = (const float*)d_in[3];
    const float* bout   = (const float*)d_in[4];
    const float* gamma1 = (const float*)d_in[5];
    const float* beta1  = (const float*)d_in[6];
    const float* gamma2 = (const float*)d_in[7];
    const float* beta2  = (const float*)d_in[8];
    const float* Wg     = (const float*)d_in[9];
    const float* bg     = (const float*)d_in[10];
    const float* Wv     = (const float*)d_in[11];
    const float* bv     = (const float*)d_in[12];
    const float* Wo     = (const float*)d_in[13];
    const float* bo     = (const float*)d_in[14];
    float* out = (float*)d_out;

    float *p_h, *p_qkv, *p_attn, *p_x1, *p_h2, *p_gate;
    cudaGetSymbolAddress((void**)&p_h,    g_h);
    cudaGetSymbolAddress((void**)&p_qkv,  g_qkv);
    cudaGetSymbolAddress((void**)&p_attn, g_attn);
    cudaGetSymbolAddress((void**)&p_x1,   g_x1);
    cudaGetSymbolAddress((void**)&p_h2,   g_h2);
    cudaGetSymbolAddress((void**)&p_gate, g_gate);

    // 1) LN1
    ln_kernel<<<NTOK, 256>>>(src, gamma1, beta1, p_h);
    // 2) QKV GEMM: [8192,1024] @ [1024,3072]
    gemm_kernel<0><<<dim3(E3 / 128, NTOK / 128), 256>>>(
        p_h, Wqkv, bqkv, nullptr, p_qkv, NTOK, E3, Edim);
    // 3) RoPE in place on q,k
    rope_kernel<<<NTOK, 512>>>(p_qkv);
    // 4) attention
    attn_kernel<<<Bdim * Hdim * Sdim, 256>>>(p_qkv, p_attn);
    // 5) out proj + residual: x1 = src + attn @ Wout + bout
    gemm_kernel<1><<<dim3(Edim / 128, NTOK / 128), 256>>>(
        p_attn, Wout, bout, src, p_x1, NTOK, Edim, Edim);
    // 6) LN2
    ln_kernel<<<NTOK, 256>>>(p_x1, gamma2, beta2, p_h2);
    // 7) gate = h2 @ Wg + bg
    gemm_kernel<0><<<dim3(FFd / 128, NTOK / 128), 256>>>(
        p_h2, Wg, bg, nullptr, p_gate, NTOK, FFd, Edim);
    // 8) gate = gelu(gate) * (h2 @ Wv + bv)   [fused epilogue, in place]
    gemm_kernel<2><<<dim3(FFd / 128, NTOK / 128), 256>>>(
        p_h2, Wv, bv, p_gate, p_gate, NTOK, FFd, Edim);
    // 9) out = x1 + gate @ Wo + bo
    gemm_kernel<1><<<dim3(Edim / 128, NTOK / 128), 256>>>(
        p_gate, Wo, bo, p_x1, out, NTOK, Edim, FFd);
}

// round 10
// speedup vs baseline: 2.2424x; 2.2424x over previous
#include <cuda_runtime.h>
#include <stdint.h>
#include <math.h>

#define Bdim 4
#define Sdim 2048
#define Edim 1024
#define Hdim 16
#define Dh   64
#define FFd  4096
#define NTOK (Bdim*Sdim)      // 8192
#define E3   (3*Edim)         // 3072
#define WIN  128              // half window
#define LNEPS 1e-5f

// ---------------- scratch (static device memory, no allocs) ----------------
__device__ float g_h   [NTOK*(size_t)Edim];
__device__ float g_qkv [NTOK*(size_t)E3];
__device__ float g_attn[NTOK*(size_t)Edim];
__device__ float g_x1  [NTOK*(size_t)Edim];
__device__ float g_h2  [NTOK*(size_t)Edim];
__device__ float g_gate[NTOK*(size_t)FFd];
// transposed weights  Wt[n][k] = W[k][n]
__device__ float g_Wt_qkv[(size_t)E3  * Edim];
__device__ float g_Wt_out[(size_t)Edim* Edim];
__device__ float g_Wt_g  [(size_t)FFd * Edim];
__device__ float g_Wt_v  [(size_t)FFd * Edim];
__device__ float g_Wt_o  [(size_t)Edim* FFd];

// =================== small PTX helpers =====================================
__device__ __forceinline__ uint32_t smem_u32(const void* p) {
    uint32_t a;
    asm("{ .reg .u64 t; cvta.to.shared.u64 t, %1; cvt.u32.u64 %0, t; }"
        : "=r"(a) : "l"(p));
    return a;
}
__device__ __forceinline__ void cp_async16(uint32_t dst, const void* src) {
    asm volatile("cp.async.cg.shared.global [%0], [%1], 16;"
                 :: "r"(dst), "l"(src) : "memory");
}
__device__ __forceinline__ void cp_commit() {
    asm volatile("cp.async.commit_group;" ::: "memory");
}
template <int N>
__device__ __forceinline__ void cp_wait() {
    asm volatile("cp.async.wait_group %0;" :: "n"(N) : "memory");
}
__device__ __forceinline__ uint32_t f2tf32(float f) {
    uint32_t u;
    asm("cvt.rna.tf32.f32 %0, %1;" : "=r"(u) : "f"(f));
    return u;
}
__device__ __forceinline__ void mma_tf32(float* c, const uint32_t* a,
                                         const uint32_t* b) {
    asm volatile(
        "mma.sync.aligned.m16n8k8.row.col.f32.tf32.tf32.f32 "
        "{%0,%1,%2,%3}, {%4,%5,%6,%7}, {%8,%9}, {%0,%1,%2,%3};"
        : "+f"(c[0]), "+f"(c[1]), "+f"(c[2]), "+f"(c[3])
        : "r"(a[0]), "r"(a[1]), "r"(a[2]), "r"(a[3]), "r"(b[0]), "r"(b[1]));
}

// =================== tf32 mma.sync GEMM ====================================
// C[M,N] = A[M,K] @ Bt[N,K]^T + bias
// EPI 0: +bias; 1: +bias+aux(residual); 2: (acc+bias)*gelu(aux)
// 128x128 CTA tile, BK=32, double-buffered cp.async, 8 warps (2m x 4n),
// each warp 64x32 via 4x4 m16n8k8 fragments.
#define PITCH 36
#define TILEF (128 * PITCH)
#define GSMEM (4 * TILEF * 4)   // bytes: 2 bufs * (A+B) * 128*36 floats

template <int EPI>
__global__ void __launch_bounds__(256, 2)
gemm_mma(const float* __restrict__ A, const float* __restrict__ Bt,
         const float* __restrict__ bias, const float* __restrict__ aux,
         float* __restrict__ C, int M, int N, int K) {
    extern __shared__ float smem[];
    float* sA = smem;              // [2][128*PITCH]
    float* sB = smem + 2 * TILEF;  // [2][128*PITCH]

    const int tid  = threadIdx.x;
    const int wid  = tid >> 5;
    const int lane = tid & 31;
    const int wm   = wid >> 2;       // 0..1
    const int wn   = wid & 3;        // 0..3
    const int bm   = blockIdx.y * 128;
    const int bn   = blockIdx.x * 128;
    const int qr   = lane >> 2;      // 0..7
    const int qc   = lane & 3;       // 0..3

    // copy mapping: 4 float4 per thread per tile
    const int crow = tid >> 1;                 // 0..127 (idx = tid + 256*i -> row = idx/8 pattern below)
    // we use idx = tid + 256*i; row = idx>>3; col4 = (idx&7)*4

    const uint32_t sa_u = smem_u32(sA);
    const uint32_t sb_u = smem_u32(sB);
    (void)crow;

    const int KT = K >> 5;   // K/32 tiles

    float acc[4][4][4];
#pragma unroll
    for (int i = 0; i < 4; i++)
#pragma unroll
        for (int j = 0; j < 4; j++)
#pragma unroll
            for (int e = 0; e < 4; e++) acc[i][j][e] = 0.f;

    // ---- prologue: load ktile 0 into buf 0
    {
        const float* Ag = A  + (size_t)bm * K;
        const float* Bg = Bt + (size_t)bn * K;
#pragma unroll
        for (int i = 0; i < 4; i++) {
            int idx = tid + 256 * i;
            int r = idx >> 3, c4 = (idx & 7) * 4;
            cp_async16(sa_u + (r * PITCH + c4) * 4, Ag + (size_t)r * K + c4);
            cp_async16(sb_u + (r * PITCH + c4) * 4, Bg + (size_t)r * K + c4);
        }
        cp_commit();
    }

    for (int kt = 0; kt < KT; kt++) {
        int buf = kt & 1;
        if (kt + 1 < KT) {
            int nb = (kt + 1) & 1;
            int k0 = (kt + 1) << 5;
            const float* Ag = A  + (size_t)bm * K + k0;
            const float* Bg = Bt + (size_t)bn * K + k0;
            uint32_t sa_o = sa_u + nb * TILEF * 4;
            uint32_t sb_o = sb_u + nb * TILEF * 4;
#pragma unroll
            for (int i = 0; i < 4; i++) {
                int idx = tid + 256 * i;
                int r = idx >> 3, c4 = (idx & 7) * 4;
                cp_async16(sa_o + (r * PITCH + c4) * 4, Ag + (size_t)r * K + c4);
                cp_async16(sb_o + (r * PITCH + c4) * 4, Bg + (size_t)r * K + c4);
            }
        }
        cp_commit();
        cp_wait<1>();
        __syncthreads();

        const float* aT = sA + buf * TILEF + (wm * 64) * PITCH;
        const float* bT = sB + buf * TILEF + (wn * 32) * PITCH;

#pragma unroll
        for (int ks = 0; ks < 4; ks++) {
            int kb = ks * 8 + qc;
            uint32_t af[4][4], bf[4][2];
#pragma unroll
            for (int mt = 0; mt < 4; mt++) {
                int r = mt * 16 + qr;
                af[mt][0] = f2tf32(aT[r * PITCH + kb]);
                af[mt][1] = f2tf32(aT[(r + 8) * PITCH + kb]);
                af[mt][2] = f2tf32(aT[r * PITCH + kb + 4]);
                af[mt][3] = f2tf32(aT[(r + 8) * PITCH + kb + 4]);
            }
#pragma unroll
            for (int nt = 0; nt < 4; nt++) {
                int n = nt * 8 + qr;
                bf[nt][0] = f2tf32(bT[n * PITCH + kb]);
                bf[nt][1] = f2tf32(bT[n * PITCH + kb + 4]);
            }
#pragma unroll
            for (int mt = 0; mt < 4; mt++)
#pragma unroll
                for (int nt = 0; nt < 4; nt++)
                    mma_tf32(acc[mt][nt], af[mt], bf[nt]);
        }
        __syncthreads();
    }

    // ---- epilogue: registers -> gmem with fused ops
#pragma unroll
    for (int mt = 0; mt < 4; mt++) {
#pragma unroll
        for (int nt = 0; nt < 4; nt++) {
            int r1 = bm + wm * 64 + mt * 16 + qr;
            int r2 = r1 + 8;
            int c  = bn + wn * 32 + nt * 8 + 2 * qc;
            float b0 = bias[c], b1 = bias[c + 1];
            float o00 = acc[mt][nt][0] + b0;
            float o01 = acc[mt][nt][1] + b1;
            float o10 = acc[mt][nt][2] + b0;
            float o11 = acc[mt][nt][3] + b1;
            if (EPI == 1) {
                float2 x0 = *(const float2*)(aux + (size_t)r1 * N + c);
                float2 x1 = *(const float2*)(aux + (size_t)r2 * N + c);
                o00 += x0.x; o01 += x0.y; o10 += x1.x; o11 += x1.y;
            }
            if (EPI == 2) {
                const float kk = 0.7071067811865476f;
                float2 x0 = *(const float2*)(aux + (size_t)r1 * N + c);
                float2 x1 = *(const float2*)(aux + (size_t)r2 * N + c);
                o00 *= 0.5f * x0.x * (1.f + erff(x0.x * kk));
                o01 *= 0.5f * x0.y * (1.f + erff(x0.y * kk));
                o10 *= 0.5f * x1.x * (1.f + erff(x1.x * kk));
                o11 *= 0.5f * x1.y * (1.f + erff(x1.y * kk));
            }
            *(float2*)(C + (size_t)r1 * N + c) = make_float2(o00, o01);
            *(float2*)(C + (size_t)r2 * N + c) = make_float2(o10, o11);
        }
    }
}

// =================== weight transpose: dst[C][R] = src[R][C] ===============
__global__ void transpose_kernel(const float* __restrict__ src,
                                 float* __restrict__ dst, int R, int C) {
    __shared__ float t[32][33];
    int x = blockIdx.x * 32 + threadIdx.x;
#pragma unroll
    for (int j = 0; j < 32; j += 8) {
        int y = blockIdx.y * 32 + threadIdx.y + j;
        t[threadIdx.y + j][threadIdx.x] = src[(size_t)y * C + x];
    }
    __syncthreads();
    int ox = blockIdx.y * 32 + threadIdx.x;
#pragma unroll
    for (int j = 0; j < 32; j += 8) {
        int oy = blockIdx.x * 32 + threadIdx.y + j;
        dst[(size_t)oy * R + ox] = t[threadIdx.x][threadIdx.y + j];
    }
}

// =================== layernorm =============================================
__global__ void ln_kernel(const float* __restrict__ x,
                          const float* __restrict__ gamma,
                          const float* __restrict__ beta,
                          float* __restrict__ out) {
    int n = blockIdx.x;
    int tid = threadIdx.x;
    const float* row = x + (size_t)n * Edim;
    float* orow = out + (size_t)n * Edim;

    float v[4];
    float s = 0.f;
#pragma unroll
    for (int i = 0; i < 4; i++) { v[i] = row[tid + 256 * i]; s += v[i]; }

    __shared__ float sh[8];
    int lane = tid & 31, warp = tid >> 5;
#pragma unroll
    for (int o = 16; o; o >>= 1) s += __shfl_xor_sync(0xffffffffu, s, o);
    if (lane == 0) sh[warp] = s;
    __syncthreads();
    if (tid < 8) {
        float t = sh[tid];
#pragma unroll
        for (int o = 4; o; o >>= 1) t += __shfl_xor_sync(0xffu, t, o);
        if (tid == 0) sh[0] = t;
    }
    __syncthreads();
    float mu = sh[0] * (1.f / Edim);
    __syncthreads();

    float s2 = 0.f;
#pragma unroll
    for (int i = 0; i < 4; i++) { float d = v[i] - mu; s2 += d * d; }
#pragma unroll
    for (int o = 16; o; o >>= 1) s2 += __shfl_xor_sync(0xffffffffu, s2, o);
    if (lane == 0) sh[warp] = s2;
    __syncthreads();
    if (tid < 8) {
        float t = sh[tid];
#pragma unroll
        for (int o = 4; o; o >>= 1) t += __shfl_xor_sync(0xffu, t, o);
        if (tid == 0) sh[0] = t;
    }
    __syncthreads();
    float var = sh[0] * (1.f / Edim);
    float r = rsqrtf(var + LNEPS);

#pragma unroll
    for (int i = 0; i < 4; i++) {
        int c = tid + 256 * i;
        orow[c] = (v[i] - mu) * r * gamma[c] + beta[c];
    }
}

// =================== RoPE ==================================================
__global__ void rope_kernel(float* __restrict__ qkv) {
    int n = blockIdx.x;
    int s = n & (Sdim - 1);
    int tid = threadIdx.x;
    int h = tid >> 5;
    int j = tid & 31;
    float inv = expf(-(float)(2 * j) * (1.f / 64.f) * 9.210340371976184f);
    float ang = (float)s * inv;
    float c, sn;
    sincosf(ang, &sn, &c);
#pragma unroll
    for (int cc = 0; cc < 2; cc++) {
        float* p = qkv + (size_t)n * E3 + cc * Edim + h * Dh;
        float x1 = p[j];
        float x2 = p[j + 32];
        p[j]      = x1 * c - x2 * sn;
        p[j + 32] = x2 * c + x1 * sn;
    }
}

// =================== sliding-window attention ==============================
__global__ void attn_kernel(const float* __restrict__ qkv,
                            float* __restrict__ out) {
    int q  = blockIdx.x & (Sdim - 1);
    int bh = blockIdx.x >> 11;
    int h  = bh & (Hdim - 1);
    int b  = bh >> 4;
    int tid = threadIdx.x;
    int lane = tid & 31, warp = tid >> 5;

    int ks = q - WIN; if (ks < 0) ks = 0;
    int ke = q + WIN; if (ke > Sdim - 1) ke = Sdim - 1;
    int nk = ke - ks + 1;

    __shared__ float qv[64];
    __shared__ float sc[257];
    __shared__ float red[8];

    const float* qp = qkv + ((size_t)(b * Sdim + q)) * E3 + h * Dh;
    if (tid < 64) qv[tid] = qp[tid];
    __syncthreads();

    for (int kk = warp; kk < nk; kk += 8) {
        const float* kp = qkv + ((size_t)(b * Sdim + ks + kk)) * E3 + Edim + h * Dh;
        float p = qv[2 * lane] * kp[2 * lane] + qv[2 * lane + 1] * kp[2 * lane + 1];
#pragma unroll
        for (int o = 16; o; o >>= 1) p += __shfl_xor_sync(0xffffffffu, p, o);
        if (lane == 0) sc[kk] = p * 0.125f;
    }
    __syncthreads();

    float m = -1e30f;
    for (int i = tid; i < nk; i += 256) m = fmaxf(m, sc[i]);
#pragma unroll
    for (int o = 16; o; o >>= 1) m = fmaxf(m, __shfl_xor_sync(0xffffffffu, m, o));
    if (lane == 0) red[warp] = m;
    __syncthreads();
    if (tid < 8) {
        float t = red[tid];
#pragma unroll
        for (int o = 4; o; o >>= 1) t = fmaxf(t, __shfl_xor_sync(0xffu, t, o));
        if (tid == 0) red[0] = t;
    }
    __syncthreads();
    m = red[0];
    __syncthreads();

    float s = 0.f;
    for (int i = tid; i < nk; i += 256) { float e = expf(sc[i] - m); sc[i] = e; s += e; }
#pragma unroll
    for (int o = 16; o; o >>= 1) s += __shfl_xor_sync(0xffffffffu, s, o);
    if (lane == 0) red[warp] = s;
    __syncthreads();
    if (tid < 8) {
        float t = red[tid];
#pragma unroll
        for (int o = 4; o; o >>= 1) t += __shfl_xor_sync(0xffu, t, o);
        if (tid == 0) red[0] = t;
    }
    __syncthreads();
    float invsum = 1.f / red[0];

    if (tid < 64) {
        float acc = 0.f;
        const float* vp = qkv + ((size_t)(b * Sdim + ks)) * E3 + 2 * Edim + h * Dh + tid;
        for (int kk = 0; kk < nk; kk++) acc += sc[kk] * vp[(size_t)kk * E3];
        out[((size_t)(b * Sdim + q)) * Edim + h * Dh + tid] = acc * invsum;
    }
}

// =================== launch ================================================
extern "C" void kernel_launch(void* const* d_in, const int* in_sizes, int n_in,
                              void* d_out, int out_size) {
    const float* src    = (const float*)d_in[0];
    const float* Wqkv   = (const float*)d_in[1];
    const float* bqkv   = (const float*)d_in[2];
    const float* Wout   = (const float*)d_in[3];
    const float* bout   = (const float*)d_in[4];
    const float* gamma1 = (const float*)d_in[5];
    const float* beta1  = (const float*)d_in[6];
    const float* gamma2 = (const float*)d_in[7];
    const float* beta2  = (const float*)d_in[8];
    const float* Wg     = (const float*)d_in[9];
    const float* bg     = (const float*)d_in[10];
    const float* Wv     = (const float*)d_in[11];
    const float* bv     = (const float*)d_in[12];
    const float* Wo     = (const float*)d_in[13];
    const float* bo     = (const float*)d_in[14];
    float* out = (float*)d_out;

    float *p_h, *p_qkv, *p_attn, *p_x1, *p_h2, *p_gate;
    float *t_qkv, *t_out, *t_g, *t_v, *t_o;
    cudaGetSymbolAddress((void**)&p_h,    g_h);
    cudaGetSymbolAddress((void**)&p_qkv,  g_qkv);
    cudaGetSymbolAddress((void**)&p_attn, g_attn);
    cudaGetSymbolAddress((void**)&p_x1,   g_x1);
    cudaGetSymbolAddress((void**)&p_h2,   g_h2);
    cudaGetSymbolAddress((void**)&p_gate, g_gate);
    cudaGetSymbolAddress((void**)&t_qkv,  g_Wt_qkv);
    cudaGetSymbolAddress((void**)&t_out,  g_Wt_out);
    cudaGetSymbolAddress((void**)&t_g,    g_Wt_g);
    cudaGetSymbolAddress((void**)&t_v,    g_Wt_v);
    cudaGetSymbolAddress((void**)&t_o,    g_Wt_o);

    cudaFuncSetAttribute(gemm_mma<0>, cudaFuncAttributeMaxDynamicSharedMemorySize, GSMEM);
    cudaFuncSetAttribute(gemm_mma<1>, cudaFuncAttributeMaxDynamicSharedMemorySize, GSMEM);
    cudaFuncSetAttribute(gemm_mma<2>, cudaFuncAttributeMaxDynamicSharedMemorySize, GSMEM);

    dim3 tb(32, 8);
    transpose_kernel<<<dim3(E3 / 32,  Edim / 32), tb>>>(Wqkv, t_qkv, Edim, E3);
    transpose_kernel<<<dim3(Edim / 32, Edim / 32), tb>>>(Wout, t_out, Edim, Edim);
    transpose_kernel<<<dim3(FFd / 32,  Edim / 32), tb>>>(Wg,   t_g,   Edim, FFd);
    transpose_kernel<<<dim3(FFd / 32,  Edim / 32), tb>>>(Wv,   t_v,   Edim, FFd);
    transpose_kernel<<<dim3(Edim / 32, FFd / 32),  tb>>>(Wo,   t_o,   FFd,  Edim);

    // 1) LN1
    ln_kernel<<<NTOK, 256>>>(src, gamma1, beta1, p_h);
    // 2) QKV GEMM
    gemm_mma<0><<<dim3(E3 / 128, NTOK / 128), 256, GSMEM>>>(
        p_h, t_qkv, bqkv, nullptr, p_qkv, NTOK, E3, Edim);
    // 3) RoPE
    rope_kernel<<<NTOK, 512>>>(p_qkv);
    // 4) attention
    attn_kernel<<<Bdim * Hdim * Sdim, 256>>>(p_qkv, p_attn);
    // 5) out proj + residual
    gemm_mma<1><<<dim3(Edim / 128, NTOK / 128), 256, GSMEM>>>(
        p_attn, t_out, bout, src, p_x1, NTOK, Edim, Edim);
    // 6) LN2
    ln_kernel<<<NTOK, 256>>>(p_x1, gamma2, beta2, p_h2);
    // 7) gate = h2 @ Wg + bg
    gemm_mma<0><<<dim3(FFd / 128, NTOK / 128), 256, GSMEM>>>(
        p_h2, t_g, bg, nullptr, p_gate, NTOK, FFd, Edim);
    // 8) gate = gelu(gate) * (h2 @ Wv + bv)
    gemm_mma<2><<<dim3(FFd / 128, NTOK / 128), 256, GSMEM>>>(
        p_h2, t_v, bv, p_gate, p_gate, NTOK, FFd, Edim);
    // 9) out = x1 + gate @ Wo + bo
    gemm_mma<1><<<dim3(Edim / 128, NTOK / 128), 256, GSMEM>>>(
        p_gate, t_o, bo, p_x1, out, NTOK, Edim, FFd);
}

// round 12
// speedup vs baseline: 2.9224x; 1.3033x over previous
#include <cuda_runtime.h>
#include <stdint.h>
#include <math.h>

#define Bdim 4
#define Sdim 2048
#define Edim 1024
#define Hdim 16
#define Dh   64
#define FFd  4096
#define NTOK (Bdim*Sdim)      // 8192
#define E3   (3*Edim)         // 3072
#define LNEPS 1e-5f

// ---------------- scratch (static device memory, no allocs) ----------------
__device__ float g_h   [NTOK*(size_t)Edim];
__device__ float g_qkv [NTOK*(size_t)E3];
__device__ float g_attn[NTOK*(size_t)Edim];
__device__ float g_x1  [NTOK*(size_t)Edim];
__device__ float g_h2  [NTOK*(size_t)Edim];
__device__ float g_gate[NTOK*(size_t)FFd];
// transposed weights  Wt[n][k] = W[k][n]
__device__ float g_Wt_qkv[(size_t)E3  * Edim];
__device__ float g_Wt_out[(size_t)Edim* Edim];
__device__ float g_Wt_g  [(size_t)FFd * Edim];
__device__ float g_Wt_v  [(size_t)FFd * Edim];
__device__ float g_Wt_o  [(size_t)Edim* FFd];

// =================== small PTX helpers =====================================
__device__ __forceinline__ uint32_t smem_u32(const void* p) {
    uint32_t a;
    asm("{ .reg .u64 t; cvta.to.shared.u64 t, %1; cvt.u32.u64 %0, t; }"
        : "=r"(a) : "l"(p));
    return a;
}
__device__ __forceinline__ void cp_async16(uint32_t dst, const void* src) {
    asm volatile("cp.async.cg.shared.global [%0], [%1], 16;"
                 :: "r"(dst), "l"(src) : "memory");
}
__device__ __forceinline__ void cp_commit() {
    asm volatile("cp.async.commit_group;" ::: "memory");
}
template <int N>
__device__ __forceinline__ void cp_wait() {
    asm volatile("cp.async.wait_group %0;" :: "n"(N) : "memory");
}
__device__ __forceinline__ uint32_t f2tf32(float f) {
    uint32_t u;
    asm("cvt.rna.tf32.f32 %0, %1;" : "=r"(u) : "f"(f));
    return u;
}
__device__ __forceinline__ void mma_tf32(float* c, const uint32_t* a,
                                         const uint32_t* b) {
    asm volatile(
        "mma.sync.aligned.m16n8k8.row.col.f32.tf32.tf32.f32 "
        "{%0,%1,%2,%3}, {%4,%5,%6,%7}, {%8,%9}, {%0,%1,%2,%3};"
        : "+f"(c[0]), "+f"(c[1]), "+f"(c[2]), "+f"(c[3])
        : "r"(a[0]), "r"(a[1]), "r"(a[2]), "r"(a[3]), "r"(b[0]), "r"(b[1]));
}

// =================== tf32 mma.sync GEMM ====================================
#define PITCH 36
#define TILEF (128 * PITCH)
#define GSMEM (4 * TILEF * 4)

template <int EPI>
__global__ void __launch_bounds__(256, 2)
gemm_mma(const float* __restrict__ A, const float* __restrict__ Bt,
         const float* __restrict__ bias, const float* __restrict__ aux,
         float* __restrict__ C, int M, int N, int K) {
    extern __shared__ float smem[];
    float* sA = smem;
    float* sB = smem + 2 * TILEF;

    const int tid  = threadIdx.x;
    const int wid  = tid >> 5;
    const int lane = tid & 31;
    const int wm   = wid >> 2;
    const int wn   = wid & 3;
    const int bm   = blockIdx.y * 128;
    const int bn   = blockIdx.x * 128;
    const int qr   = lane >> 2;
    const int qc   = lane & 3;

    const uint32_t sa_u = smem_u32(sA);
    const uint32_t sb_u = smem_u32(sB);
    const int KT = K >> 5;

    float acc[4][4][4];
#pragma unroll
    for (int i = 0; i < 4; i++)
#pragma unroll
        for (int j = 0; j < 4; j++)
#pragma unroll
            for (int e = 0; e < 4; e++) acc[i][j][e] = 0.f;

    {
        const float* Ag = A  + (size_t)bm * K;
        const float* Bg = Bt + (size_t)bn * K;
#pragma unroll
        for (int i = 0; i < 4; i++) {
            int idx = tid + 256 * i;
            int r = idx >> 3, c4 = (idx & 7) * 4;
            cp_async16(sa_u + (r * PITCH + c4) * 4, Ag + (size_t)r * K + c4);
            cp_async16(sb_u + (r * PITCH + c4) * 4, Bg + (size_t)r * K + c4);
        }
        cp_commit();
    }

    for (int kt = 0; kt < KT; kt++) {
        int buf = kt & 1;
        if (kt + 1 < KT) {
            int nb = (kt + 1) & 1;
            int k0 = (kt + 1) << 5;
            const float* Ag = A  + (size_t)bm * K + k0;
            const float* Bg = Bt + (size_t)bn * K + k0;
            uint32_t sa_o = sa_u + nb * TILEF * 4;
            uint32_t sb_o = sb_u + nb * TILEF * 4;
#pragma unroll
            for (int i = 0; i < 4; i++) {
                int idx = tid + 256 * i;
                int r = idx >> 3, c4 = (idx & 7) * 4;
                cp_async16(sa_o + (r * PITCH + c4) * 4, Ag + (size_t)r * K + c4);
                cp_async16(sb_o + (r * PITCH + c4) * 4, Bg + (size_t)r * K + c4);
            }
        }
        cp_commit();
        cp_wait<1>();
        __syncthreads();

        const float* aT = sA + buf * TILEF + (wm * 64) * PITCH;
        const float* bT = sB + buf * TILEF + (wn * 32) * PITCH;

#pragma unroll
        for (int ks = 0; ks < 4; ks++) {
            int kb = ks * 8 + qc;
            uint32_t af[4][4], bf[4][2];
#pragma unroll
            for (int mt = 0; mt < 4; mt++) {
                int r = mt * 16 + qr;
                af[mt][0] = f2tf32(aT[r * PITCH + kb]);
                af[mt][1] = f2tf32(aT[(r + 8) * PITCH + kb]);
                af[mt][2] = f2tf32(aT[r * PITCH + kb + 4]);
                af[mt][3] = f2tf32(aT[(r + 8) * PITCH + kb + 4]);
            }
#pragma unroll
            for (int nt = 0; nt < 4; nt++) {
                int n = nt * 8 + qr;
                bf[nt][0] = f2tf32(bT[n * PITCH + kb]);
                bf[nt][1] = f2tf32(bT[n * PITCH + kb + 4]);
            }
#pragma unroll
            for (int mt = 0; mt < 4; mt++)
#pragma unroll
                for (int nt = 0; nt < 4; nt++)
                    mma_tf32(acc[mt][nt], af[mt], bf[nt]);
        }
        __syncthreads();
    }

#pragma unroll
    for (int mt = 0; mt < 4; mt++) {
#pragma unroll
        for (int nt = 0; nt < 4; nt++) {
            int r1 = bm + wm * 64 + mt * 16 + qr;
            int r2 = r1 + 8;
            int c  = bn + wn * 32 + nt * 8 + 2 * qc;
            float b0 = bias[c], b1 = bias[c + 1];
            float o00 = acc[mt][nt][0] + b0;
            float o01 = acc[mt][nt][1] + b1;
            float o10 = acc[mt][nt][2] + b0;
            float o11 = acc[mt][nt][3] + b1;
            if (EPI == 1) {
                float2 x0 = *(const float2*)(aux + (size_t)r1 * N + c);
                float2 x1 = *(const float2*)(aux + (size_t)r2 * N + c);
                o00 += x0.x; o01 += x0.y; o10 += x1.x; o11 += x1.y;
            }
            if (EPI == 2) {
                const float kk = 0.7071067811865476f;
                float2 x0 = *(const float2*)(aux + (size_t)r1 * N + c);
                float2 x1 = *(const float2*)(aux + (size_t)r2 * N + c);
                o00 *= 0.5f * x0.x * (1.f + erff(x0.x * kk));
                o01 *= 0.5f * x0.y * (1.f + erff(x0.y * kk));
                o10 *= 0.5f * x1.x * (1.f + erff(x1.x * kk));
                o11 *= 0.5f * x1.y * (1.f + erff(x1.y * kk));
            }
            *(float2*)(C + (size_t)r1 * N + c) = make_float2(o00, o01);
            *(float2*)(C + (size_t)r2 * N + c) = make_float2(o10, o11);
        }
    }
}

// =================== weight transpose ======================================
__global__ void transpose_kernel(const float* __restrict__ src,
                                 float* __restrict__ dst, int R, int C) {
    __shared__ float t[32][33];
    int x = blockIdx.x * 32 + threadIdx.x;
#pragma unroll
    for (int j = 0; j < 32; j += 8) {
        int y = blockIdx.y * 32 + threadIdx.y + j;
        t[threadIdx.y + j][threadIdx.x] = src[(size_t)y * C + x];
    }
    __syncthreads();
    int ox = blockIdx.y * 32 + threadIdx.x;
#pragma unroll
    for (int j = 0; j < 32; j += 8) {
        int oy = blockIdx.x * 32 + threadIdx.y + j;
        dst[(size_t)oy * R + ox] = t[threadIdx.x][threadIdx.y + j];
    }
}

// =================== layernorm =============================================
__global__ void ln_kernel(const float* __restrict__ x,
                          const float* __restrict__ gamma,
                          const float* __restrict__ beta,
                          float* __restrict__ out) {
    int n = blockIdx.x;
    int tid = threadIdx.x;
    const float* row = x + (size_t)n * Edim;
    float* orow = out + (size_t)n * Edim;

    float v[4];
    float s = 0.f;
#pragma unroll
    for (int i = 0; i < 4; i++) { v[i] = row[tid + 256 * i]; s += v[i]; }

    __shared__ float sh[8];
    int lane = tid & 31, warp = tid >> 5;
#pragma unroll
    for (int o = 16; o; o >>= 1) s += __shfl_xor_sync(0xffffffffu, s, o);
    if (lane == 0) sh[warp] = s;
    __syncthreads();
    if (tid < 8) {
        float t = sh[tid];
#pragma unroll
        for (int o = 4; o; o >>= 1) t += __shfl_xor_sync(0xffu, t, o);
        if (tid == 0) sh[0] = t;
    }
    __syncthreads();
    float mu = sh[0] * (1.f / Edim);
    __syncthreads();

    float s2 = 0.f;
#pragma unroll
    for (int i = 0; i < 4; i++) { float d = v[i] - mu; s2 += d * d; }
#pragma unroll
    for (int o = 16; o; o >>= 1) s2 += __shfl_xor_sync(0xffffffffu, s2, o);
    if (lane == 0) sh[warp] = s2;
    __syncthreads();
    if (tid < 8) {
        float t = sh[tid];
#pragma unroll
        for (int o = 4; o; o >>= 1) t += __shfl_xor_sync(0xffu, t, o);
        if (tid == 0) sh[0] = t;
    }
    __syncthreads();
    float var = sh[0] * (1.f / Edim);
    float r = rsqrtf(var + LNEPS);

#pragma unroll
    for (int i = 0; i < 4; i++) {
        int c = tid + 256 * i;
        orow[c] = (v[i] - mu) * r * gamma[c] + beta[c];
    }
}

// =================== RoPE ==================================================
__global__ void rope_kernel(float* __restrict__ qkv) {
    int n = blockIdx.x;
    int s = n & (Sdim - 1);
    int tid = threadIdx.x;
    int h = tid >> 5;
    int j = tid & 31;
    float inv = expf(-(float)(2 * j) * (1.f / 64.f) * 9.210340371976184f);
    float ang = (float)s * inv;
    float c, sn;
    sincosf(ang, &sn, &c);
#pragma unroll
    for (int cc = 0; cc < 2; cc++) {
        float* p = qkv + (size_t)n * E3 + cc * Edim + h * Dh;
        float x1 = p[j];
        float x2 = p[j + 32];
        p[j]      = x1 * c - x2 * sn;
        p[j + 32] = x2 * c + x1 * sn;
    }
}

// =================== flash-style sliding-window attention ==================
// CTA = (qtile of 64, h, b). 256 threads. 5 key chunks of 64.
#define QT 64
#define KC 64
#define PQ 68                      // q/k/v smem pitch (floats)
#define PS 65                      // probs pitch
#define ATT_SQ   0                 // [QT*PQ]
#define ATT_SK   (QT*PQ)           // [KC*PQ]
#define ATT_SV   (QT*PQ + KC*PQ)   // [KC*PQ]
#define ATT_SS   (QT*PQ + 2*KC*PQ) // [QT*PS]
#define ATT_AUX  (ATT_SS + QT*PS)  // fac[QT], m[QT], l[QT]
#define ATT_FLOATS (ATT_AUX + 3*QT)
#define ATT_SMEM (ATT_FLOATS * 4)

__global__ void __launch_bounds__(256, 2)
fattn_kernel(const float* __restrict__ qkv, float* __restrict__ out) {
    extern __shared__ float sm[];
    float* sQ = sm + ATT_SQ;
    float* sK = sm + ATT_SK;
    float* sV = sm + ATT_SV;
    float* sS = sm + ATT_SS;
    float* s_fac = sm + ATT_AUX;
    float* s_m   = s_fac + QT;
    float* s_l   = s_m + QT;

    const int tid = threadIdx.x;
    const int q0  = blockIdx.x * QT;
    const int h   = blockIdx.y;
    const int b   = blockIdx.z;

    // load Q tile (64 rows x 64 cols)
#pragma unroll
    for (int i = 0; i < 4; i++) {
        int idx = tid + 256 * i;                 // float4 index
        int r = idx >> 4, c4 = (idx & 15) * 4;
        float4 v = *(const float4*)(qkv + ((size_t)(b * Sdim + q0 + r)) * E3 + h * Dh + c4);
        *(float4*)(sQ + r * PQ + c4) = v;
    }
    if (tid < QT) { s_m[tid] = -1e30f; s_l[tid] = 0.f; }

    float acc[16];
#pragma unroll
    for (int e = 0; e < 16; e++) acc[e] = 0.f;
    const int aq = tid >> 2;            // AV: query row
    const int ad = (tid & 3) * 16;      // AV: d offset
    const int qg = tid >> 4;            // scores: 4-query group 0..15
    const int kg = tid & 15;            // scores: key lane 0..15
    __syncthreads();

    for (int ch = 0; ch < 5; ch++) {
        int ks = q0 - 128 + ch * KC;
        if (ks + KC - 1 < 0 || ks >= Sdim) continue;   // uniform over block

        // load K,V chunk
#pragma unroll
        for (int i = 0; i < 4; i++) {
            int idx = tid + 256 * i;
            int r = idx >> 4, c4 = (idx & 15) * 4;
            const float* base = qkv + ((size_t)(b * Sdim + ks + r)) * E3 + h * Dh + c4;
            *(float4*)(sK + r * PQ + c4) = *(const float4*)(base + Edim);
            *(float4*)(sV + r * PQ + c4) = *(const float4*)(base + 2 * Edim);
        }
        __syncthreads();

        // scores: 4 queries (qg*4+j) x 4 keys (kg+16i)
        float sc[4][4];
#pragma unroll
        for (int j = 0; j < 4; j++)
#pragma unroll
            for (int i = 0; i < 4; i++) sc[j][i] = 0.f;
        for (int kd = 0; kd < Dh; kd += 4) {
            float4 qv[4], kv[4];
#pragma unroll
            for (int j = 0; j < 4; j++) qv[j] = *(const float4*)(sQ + (qg * 4 + j) * PQ + kd);
#pragma unroll
            for (int i = 0; i < 4; i++) kv[i] = *(const float4*)(sK + (kg + 16 * i) * PQ + kd);
#pragma unroll
            for (int j = 0; j < 4; j++)
#pragma unroll
                for (int i = 0; i < 4; i++)
                    sc[j][i] += qv[j].x * kv[i].x + qv[j].y * kv[i].y
                              + qv[j].z * kv[i].z + qv[j].w * kv[i].w;
        }
        // scale + mask
#pragma unroll
        for (int j = 0; j < 4; j++) {
            int qq = q0 + qg * 4 + j;
#pragma unroll
            for (int i = 0; i < 4; i++) {
                int kk = ks + kg + 16 * i;
                float s = sc[j][i] * 0.125f;
                int d = qq - kk; if (d < 0) d = -d;
                sc[j][i] = (d <= 128) ? s : -1e9f;
            }
        }
        // per-row max over the 16 kg lanes
        float rmax[4];
#pragma unroll
        for (int j = 0; j < 4; j++)
            rmax[j] = fmaxf(fmaxf(sc[j][0], sc[j][1]), fmaxf(sc[j][2], sc[j][3]));
#pragma unroll
        for (int o = 1; o < 16; o <<= 1)
#pragma unroll
            for (int j = 0; j < 4; j++)
                rmax[j] = fmaxf(rmax[j], __shfl_xor_sync(0xffffffffu, rmax[j], o));

        float fac[4], rsum[4], mnew[4];
#pragma unroll
        for (int j = 0; j < 4; j++) {
            float mo = s_m[qg * 4 + j];
            float mn = fmaxf(mo, rmax[j]);
            float sum = 0.f;
#pragma unroll
            for (int i = 0; i < 4; i++) {
                float p = __expf(sc[j][i] - mn);
                sS[(qg * 4 + j) * PS + kg + 16 * i] = p;
                sum += p;
            }
            rsum[j] = sum;
            fac[j]  = __expf(mo - mn);
            mnew[j] = mn;
        }
#pragma unroll
        for (int o = 1; o < 16; o <<= 1)
#pragma unroll
            for (int j = 0; j < 4; j++)
                rsum[j] += __shfl_xor_sync(0xffffffffu, rsum[j], o);
        if (kg == 0) {
#pragma unroll
            for (int j = 0; j < 4; j++) {
                int q = qg * 4 + j;
                s_m[q] = mnew[j];
                s_l[q] = s_l[q] * fac[j] + rsum[j];
                s_fac[q] = fac[j];
            }
        }
        __syncthreads();

        // AV: each thread: query aq, d slice [ad, ad+16)
        float f = s_fac[aq];
#pragma unroll
        for (int e = 0; e < 16; e++) acc[e] *= f;
        const float* vb = sV + ad;
        const float* pr = sS + aq * PS;
        for (int k = 0; k < KC; k++) {
            float p = pr[k];
            float4 v0 = *(const float4*)(vb + k * PQ);
            float4 v1 = *(const float4*)(vb + k * PQ + 4);
            float4 v2 = *(const float4*)(vb + k * PQ + 8);
            float4 v3 = *(const float4*)(vb + k * PQ + 12);
            acc[0]  += p * v0.x; acc[1]  += p * v0.y; acc[2]  += p * v0.z; acc[3]  += p * v0.w;
            acc[4]  += p * v1.x; acc[5]  += p * v1.y; acc[6]  += p * v1.z; acc[7]  += p * v1.w;
            acc[8]  += p * v2.x; acc[9]  += p * v2.y; acc[10] += p * v2.z; acc[11] += p * v2.w;
            acc[12] += p * v3.x; acc[13] += p * v3.y; acc[14] += p * v3.z; acc[15] += p * v3.w;
        }
        __syncthreads();
    }

    float invl = 1.f / s_l[aq];
    float* op = out + ((size_t)(b * Sdim + q0 + aq)) * Edim + h * Dh + ad;
#pragma unroll
    for (int e = 0; e < 16; e += 4) {
        float4 v = make_float4(acc[e] * invl, acc[e + 1] * invl,
                               acc[e + 2] * invl, acc[e + 3] * invl);
        *(float4*)(op + e) = v;
    }
}

// =================== launch ================================================
extern "C" void kernel_launch(void* const* d_in, const int* in_sizes, int n_in,
                              void* d_out, int out_size) {
    const float* src    = (const float*)d_in[0];
    const float* Wqkv   = (const float*)d_in[1];
    const float* bqkv   = (const float*)d_in[2];
    const float* Wout   = (const float*)d_in[3];
    const float* bout   = (const float*)d_in[4];
    const float* gamma1 = (const float*)d_in[5];
    const float* beta1  = (const float*)d_in[6];
    const float* gamma2 = (const float*)d_in[7];
    const float* beta2  = (const float*)d_in[8];
    const float* Wg     = (const float*)d_in[9];
    const float* bg     = (const float*)d_in[10];
    const float* Wv     = (const float*)d_in[11];
    const float* bv     = (const float*)d_in[12];
    const float* Wo     = (const float*)d_in[13];
    const float* bo     = (const float*)d_in[14];
    float* out = (float*)d_out;

    float *p_h, *p_qkv, *p_attn, *p_x1, *p_h2, *p_gate;
    float *t_qkv, *t_out, *t_g, *t_v, *t_o;
    cudaGetSymbolAddress((void**)&p_h,    g_h);
    cudaGetSymbolAddress((void**)&p_qkv,  g_qkv);
    cudaGetSymbolAddress((void**)&p_attn, g_attn);
    cudaGetSymbolAddress((void**)&p_x1,   g_x1);
    cudaGetSymbolAddress((void**)&p_h2,   g_h2);
    cudaGetSymbolAddress((void**)&p_gate, g_gate);
    cudaGetSymbolAddress((void**)&t_qkv,  g_Wt_qkv);
    cudaGetSymbolAddress((void**)&t_out,  g_Wt_out);
    cudaGetSymbolAddress((void**)&t_g,    g_Wt_g);
    cudaGetSymbolAddress((void**)&t_v,    g_Wt_v);
    cudaGetSymbolAddress((void**)&t_o,    g_Wt_o);

    cudaFuncSetAttribute(gemm_mma<0>, cudaFuncAttributeMaxDynamicSharedMemorySize, GSMEM);
    cudaFuncSetAttribute(gemm_mma<1>, cudaFuncAttributeMaxDynamicSharedMemorySize, GSMEM);
    cudaFuncSetAttribute(gemm_mma<2>, cudaFuncAttributeMaxDynamicSharedMemorySize, GSMEM);
    cudaFuncSetAttribute(fattn_kernel, cudaFuncAttributeMaxDynamicSharedMemorySize, ATT_SMEM);

    dim3 tb(32, 8);
    transpose_kernel<<<dim3(E3 / 32,  Edim / 32), tb>>>(Wqkv, t_qkv, Edim, E3);
    transpose_kernel<<<dim3(Edim / 32, Edim / 32), tb>>>(Wout, t_out, Edim, Edim);
    transpose_kernel<<<dim3(FFd / 32,  Edim / 32), tb>>>(Wg,   t_g,   Edim, FFd);
    transpose_kernel<<<dim3(FFd / 32,  Edim / 32), tb>>>(Wv,   t_v,   Edim, FFd);
    transpose_kernel<<<dim3(Edim / 32, FFd / 32),  tb>>>(Wo,   t_o,   FFd,  Edim);

    // 1) LN1
    ln_kernel<<<NTOK, 256>>>(src, gamma1, beta1, p_h);
    // 2) QKV GEMM
    gemm_mma<0><<<dim3(E3 / 128, NTOK / 128), 256, GSMEM>>>(
        p_h, t_qkv, bqkv, nullptr, p_qkv, NTOK, E3, Edim);
    // 3) RoPE
    rope_kernel<<<NTOK, 512>>>(p_qkv);
    // 4) flash attention
    fattn_kernel<<<dim3(Sdim / QT, Hdim, Bdim), 256, ATT_SMEM>>>(p_qkv, p_attn);
    // 5) out proj + residual
    gemm_mma<1><<<dim3(Edim / 128, NTOK / 128), 256, GSMEM>>>(
        p_attn, t_out, bout, src, p_x1, NTOK, Edim, Edim);
    // 6) LN2
    ln_kernel<<<NTOK, 256>>>(p_x1, gamma2, beta2, p_h2);
    // 7) gate = h2 @ Wg + bg
    gemm_mma<0><<<dim3(FFd / 128, NTOK / 128), 256, GSMEM>>>(
        p_h2, t_g, bg, nullptr, p_gate, NTOK, FFd, Edim);
    // 8) gate = gelu(gate) * (h2 @ Wv + bv)
    gemm_mma<2><<<dim3(FFd / 128, NTOK / 128), 256, GSMEM>>>(
        p_h2, t_v, bv, p_gate, p_gate, NTOK, FFd, Edim);
    // 9) out = x1 + gate @ Wo + bo
    gemm_mma<1><<<dim3(Edim / 128, NTOK / 128), 256, GSMEM>>>(
        p_gate, t_o, bo, p_x1, out, NTOK, Edim, FFd);
}

// round 14
// speedup vs baseline: 4.3040x; 1.4728x over previous
#include <cuda_runtime.h>
#include <cuda_fp16.h>
#include <stdint.h>
#include <math.h>

#define Bdim 4
#define Sdim 2048
#define Edim 1024
#define Hdim 16
#define Dh   64
#define FFd  4096
#define NTOK (Bdim*Sdim)      // 8192
#define E3   (3*Edim)         // 3072
#define LNEPS 1e-5f

// ---------------- scratch (static device memory, no allocs) ----------------
__device__ float  g_qkv [NTOK*(size_t)E3];    // f32 (RoPE + attention precision)
__device__ float  g_x1  [NTOK*(size_t)Edim];  // residual 1 (f32)
__device__ float  g_gate[NTOK*(size_t)FFd];   // gate (f32, for gelu aux)
__device__ __half g_h_h   [NTOK*(size_t)Edim]; // ln1 out (half, GEMM A)
__device__ __half g_h2_h  [NTOK*(size_t)Edim]; // ln2 out (half)
__device__ __half g_attn_h[NTOK*(size_t)Edim]; // attention out (half)
__device__ __half g_act_h [NTOK*(size_t)FFd];  // gelu(gate)*val (half)
// transposed half weights  Wt[n][k] = W[k][n]
__device__ __half g_Wt_qkv[(size_t)E3  * Edim];
__device__ __half g_Wt_out[(size_t)Edim* Edim];
__device__ __half g_Wt_g  [(size_t)FFd * Edim];
__device__ __half g_Wt_v  [(size_t)FFd * Edim];
__device__ __half g_Wt_o  [(size_t)Edim* FFd];

// =================== small PTX helpers =====================================
__device__ __forceinline__ uint32_t smem_u32(const void* p) {
    uint32_t a;
    asm("{ .reg .u64 t; cvta.to.shared.u64 t, %1; cvt.u32.u64 %0, t; }"
        : "=r"(a) : "l"(p));
    return a;
}
__device__ __forceinline__ void cp_async16(uint32_t dst, const void* src) {
    asm volatile("cp.async.cg.shared.global [%0], [%1], 16;"
                 :: "r"(dst), "l"(src) : "memory");
}
__device__ __forceinline__ void cp_commit() {
    asm volatile("cp.async.commit_group;" ::: "memory");
}
template <int N>
__device__ __forceinline__ void cp_wait() {
    asm volatile("cp.async.wait_group %0;" :: "n"(N) : "memory");
}
__device__ __forceinline__ void mma_f16(float* c, const uint32_t* a,
                                        const uint32_t* b) {
    asm volatile(
        "mma.sync.aligned.m16n8k16.row.col.f32.f16.f16.f32 "
        "{%0,%1,%2,%3}, {%4,%5,%6,%7}, {%8,%9}, {%0,%1,%2,%3};"
        : "+f"(c[0]), "+f"(c[1]), "+f"(c[2]), "+f"(c[3])
        : "r"(a[0]), "r"(a[1]), "r"(a[2]), "r"(a[3]), "r"(b[0]), "r"(b[1]));
}

// =================== fp16 mma.sync GEMM ====================================
// C[M,N] = A[M,K](half) @ Bt[N,K](half)^T + bias(f32)
// EPI 0: +bias; 1: +bias+aux(residual f32); 2: (acc+bias)*gelu(aux f32)
// 128x128 CTA tile, BK=64, double-buffered cp.async, 8 warps (2m x 4n),
// each warp 64x32 via 4x4 m16n8k16 fragments.
#define BKH 64
#define PH  72                  // halves per smem row (144 B)
#define ATILE (128 * PH)        // halves per (A or B) buffer
#define GSMEM (4 * ATILE * 2)   // bytes: 2 bufs * (A+B)

template <int EPI, typename OutT>
__global__ void __launch_bounds__(256, 2)
gemm_h(const __half* __restrict__ A, const __half* __restrict__ Bt,
       const float* __restrict__ bias, const float* __restrict__ aux,
       OutT* __restrict__ C, int M, int N, int K) {
    extern __shared__ __half smh[];
    __half* sA = smh;               // [2][ATILE]
    __half* sB = smh + 2 * ATILE;   // [2][ATILE]

    const int tid  = threadIdx.x;
    const int wid  = tid >> 5;
    const int lane = tid & 31;
    const int wm   = wid >> 2;       // 0..1
    const int wn   = wid & 3;        // 0..3
    const int bm   = blockIdx.y * 128;
    const int bn   = blockIdx.x * 128;
    const int qr   = lane >> 2;      // 0..7
    const int qc   = lane & 3;       // 0..3

    const uint32_t sa_u = smem_u32(sA);
    const uint32_t sb_u = smem_u32(sB);
    const int KT = K / BKH;

    float acc[4][4][4];
#pragma unroll
    for (int i = 0; i < 4; i++)
#pragma unroll
        for (int j = 0; j < 4; j++)
#pragma unroll
            for (int e = 0; e < 4; e++) acc[i][j][e] = 0.f;

    // copy mapping: tile is 128 rows x 64 halves (128B) = 1024 16B-chunks
    // idx = tid + 256*i ; r = idx>>3 ; c8 = (idx&7)*8 halves
    {
        const __half* Ag = A  + (size_t)bm * K;
        const __half* Bg = Bt + (size_t)bn * K;
#pragma unroll
        for (int i = 0; i < 4; i++) {
            int idx = tid + 256 * i;
            int r = idx >> 3, c8 = (idx & 7) * 8;
            cp_async16(sa_u + (r * PH + c8) * 2, Ag + (size_t)r * K + c8);
            cp_async16(sb_u + (r * PH + c8) * 2, Bg + (size_t)r * K + c8);
        }
        cp_commit();
    }

    for (int kt = 0; kt < KT; kt++) {
        int buf = kt & 1;
        if (kt + 1 < KT) {
            int nb = (kt + 1) & 1;
            int k0 = (kt + 1) * BKH;
            const __half* Ag = A  + (size_t)bm * K + k0;
            const __half* Bg = Bt + (size_t)bn * K + k0;
            uint32_t sa_o = sa_u + nb * ATILE * 2;
            uint32_t sb_o = sb_u + nb * ATILE * 2;
#pragma unroll
            for (int i = 0; i < 4; i++) {
                int idx = tid + 256 * i;
                int r = idx >> 3, c8 = (idx & 7) * 8;
                cp_async16(sa_o + (r * PH + c8) * 2, Ag + (size_t)r * K + c8);
                cp_async16(sb_o + (r * PH + c8) * 2, Bg + (size_t)r * K + c8);
            }
        }
        cp_commit();
        cp_wait<1>();
        __syncthreads();

        const __half* aT = sA + buf * ATILE + (wm * 64) * PH;
        const __half* bT = sB + buf * ATILE + (wn * 32) * PH;

#pragma unroll
        for (int ks = 0; ks < 4; ks++) {           // 4 x k16 = BK 64
            int kb = ks * 16 + 2 * qc;
            uint32_t af[4][4], bf[4][2];
#pragma unroll
            for (int mt = 0; mt < 4; mt++) {
                int r = mt * 16 + qr;
                af[mt][0] = *(const uint32_t*)(aT + r * PH + kb);
                af[mt][1] = *(const uint32_t*)(aT + (r + 8) * PH + kb);
                af[mt][2] = *(const uint32_t*)(aT + r * PH + kb + 8);
                af[mt][3] = *(const uint32_t*)(aT + (r + 8) * PH + kb + 8);
            }
#pragma unroll
            for (int nt = 0; nt < 4; nt++) {
                int n = nt * 8 + qr;
                bf[nt][0] = *(const uint32_t*)(bT + n * PH + kb);
                bf[nt][1] = *(const uint32_t*)(bT + n * PH + kb + 8);
            }
#pragma unroll
            for (int mt = 0; mt < 4; mt++)
#pragma unroll
                for (int nt = 0; nt < 4; nt++)
                    mma_f16(acc[mt][nt], af[mt], bf[nt]);
        }
        __syncthreads();
    }

    // ---- epilogue
#pragma unroll
    for (int mt = 0; mt < 4; mt++) {
#pragma unroll
        for (int nt = 0; nt < 4; nt++) {
            int r1 = bm + wm * 64 + mt * 16 + qr;
            int r2 = r1 + 8;
            int c  = bn + wn * 32 + nt * 8 + 2 * qc;
            float b0 = bias[c], b1 = bias[c + 1];
            float o00 = acc[mt][nt][0] + b0;
            float o01 = acc[mt][nt][1] + b1;
            float o10 = acc[mt][nt][2] + b0;
            float o11 = acc[mt][nt][3] + b1;
            if (EPI == 1) {
                float2 x0 = *(const float2*)(aux + (size_t)r1 * N + c);
                float2 x1 = *(const float2*)(aux + (size_t)r2 * N + c);
                o00 += x0.x; o01 += x0.y; o10 += x1.x; o11 += x1.y;
            }
            if (EPI == 2) {
                const float kk = 0.7071067811865476f;
                float2 x0 = *(const float2*)(aux + (size_t)r1 * N + c);
                float2 x1 = *(const float2*)(aux + (size_t)r2 * N + c);
                o00 *= 0.5f * x0.x * (1.f + erff(x0.x * kk));
                o01 *= 0.5f * x0.y * (1.f + erff(x0.y * kk));
                o10 *= 0.5f * x1.x * (1.f + erff(x1.x * kk));
                o11 *= 0.5f * x1.y * (1.f + erff(x1.y * kk));
            }
            if (sizeof(OutT) == 4) {
                *(float2*)((float*)C + (size_t)r1 * N + c) = make_float2(o00, o01);
                *(float2*)((float*)C + (size_t)r2 * N + c) = make_float2(o10, o11);
            } else {
                *(__half2*)((__half*)C + (size_t)r1 * N + c) = __floats2half2_rn(o00, o01);
                *(__half2*)((__half*)C + (size_t)r2 * N + c) = __floats2half2_rn(o10, o11);
            }
        }
    }
}

// =================== weight transpose (f32 -> half) ========================
__global__ void transpose_h_kernel(const float* __restrict__ src,
                                   __half* __restrict__ dst, int R, int C) {
    __shared__ float t[32][33];
    int x = blockIdx.x * 32 + threadIdx.x;
#pragma unroll
    for (int j = 0; j < 32; j += 8) {
        int y = blockIdx.y * 32 + threadIdx.y + j;
        t[threadIdx.y + j][threadIdx.x] = src[(size_t)y * C + x];
    }
    __syncthreads();
    int ox = blockIdx.y * 32 + threadIdx.x;
#pragma unroll
    for (int j = 0; j < 32; j += 8) {
        int oy = blockIdx.x * 32 + threadIdx.y + j;
        dst[(size_t)oy * R + ox] = __float2half_rn(t[threadIdx.x][threadIdx.y + j]);
    }
}

// =================== layernorm (f32 in -> half out) ========================
__global__ void ln_kernel(const float* __restrict__ x,
                          const float* __restrict__ gamma,
                          const float* __restrict__ beta,
                          __half* __restrict__ out) {
    int n = blockIdx.x;
    int tid = threadIdx.x;
    const float* row = x + (size_t)n * Edim;
    __half* orow = out + (size_t)n * Edim;

    float v[4];
    float s = 0.f;
#pragma unroll
    for (int i = 0; i < 4; i++) { v[i] = row[tid + 256 * i]; s += v[i]; }

    __shared__ float sh[8];
    int lane = tid & 31, warp = tid >> 5;
#pragma unroll
    for (int o = 16; o; o >>= 1) s += __shfl_xor_sync(0xffffffffu, s, o);
    if (lane == 0) sh[warp] = s;
    __syncthreads();
    if (tid < 8) {
        float t = sh[tid];
#pragma unroll
        for (int o = 4; o; o >>= 1) t += __shfl_xor_sync(0xffu, t, o);
        if (tid == 0) sh[0] = t;
    }
    __syncthreads();
    float mu = sh[0] * (1.f / Edim);
    __syncthreads();

    float s2 = 0.f;
#pragma unroll
    for (int i = 0; i < 4; i++) { float d = v[i] - mu; s2 += d * d; }
#pragma unroll
    for (int o = 16; o; o >>= 1) s2 += __shfl_xor_sync(0xffffffffu, s2, o);
    if (lane == 0) sh[warp] = s2;
    __syncthreads();
    if (tid < 8) {
        float t = sh[tid];
#pragma unroll
        for (int o = 4; o; o >>= 1) t += __shfl_xor_sync(0xffu, t, o);
        if (tid == 0) sh[0] = t;
    }
    __syncthreads();
    float var = sh[0] * (1.f / Edim);
    float r = rsqrtf(var + LNEPS);

#pragma unroll
    for (int i = 0; i < 4; i++) {
        int c = tid + 256 * i;
        orow[c] = __float2half_rn((v[i] - mu) * r * gamma[c] + beta[c]);
    }
}

// =================== RoPE (f32, in place) ==================================
__global__ void rope_kernel(float* __restrict__ qkv) {
    int n = blockIdx.x;
    int s = n & (Sdim - 1);
    int tid = threadIdx.x;
    int h = tid >> 5;
    int j = tid & 31;
    float inv = expf(-(float)(2 * j) * (1.f / 64.f) * 9.210340371976184f);
    float ang = (float)s * inv;
    float c, sn;
    sincosf(ang, &sn, &c);
#pragma unroll
    for (int cc = 0; cc < 2; cc++) {
        float* p = qkv + (size_t)n * E3 + cc * Edim + h * Dh;
        float x1 = p[j];
        float x2 = p[j + 32];
        p[j]      = x1 * c - x2 * sn;
        p[j + 32] = x2 * c + x1 * sn;
    }
}

// =================== flash-style sliding-window attention ==================
#define QT 64
#define KC 64
#define PQ 68
#define PS 65
#define ATT_SQ   0
#define ATT_SK   (QT*PQ)
#define ATT_SV   (QT*PQ + KC*PQ)
#define ATT_SS   (QT*PQ + 2*KC*PQ)
#define ATT_AUX  (ATT_SS + QT*PS)
#define ATT_FLOATS (ATT_AUX + 3*QT)
#define ATT_SMEM (ATT_FLOATS * 4)

__global__ void __launch_bounds__(256, 2)
fattn_kernel(const float* __restrict__ qkv, __half* __restrict__ out) {
    extern __shared__ float sm[];
    float* sQ = sm + ATT_SQ;
    float* sK = sm + ATT_SK;
    float* sV = sm + ATT_SV;
    float* sS = sm + ATT_SS;
    float* s_fac = sm + ATT_AUX;
    float* s_m   = s_fac + QT;
    float* s_l   = s_m + QT;

    const int tid = threadIdx.x;
    const int q0  = blockIdx.x * QT;
    const int h   = blockIdx.y;
    const int b   = blockIdx.z;

#pragma unroll
    for (int i = 0; i < 4; i++) {
        int idx = tid + 256 * i;
        int r = idx >> 4, c4 = (idx & 15) * 4;
        float4 v = *(const float4*)(qkv + ((size_t)(b * Sdim + q0 + r)) * E3 + h * Dh + c4);
        *(float4*)(sQ + r * PQ + c4) = v;
    }
    if (tid < QT) { s_m[tid] = -1e30f; s_l[tid] = 0.f; }

    float acc[16];
#pragma unroll
    for (int e = 0; e < 16; e++) acc[e] = 0.f;
    const int aq = tid >> 2;
    const int ad = (tid & 3) * 16;
    const int qg = tid >> 4;
    const int kg = tid & 15;
    __syncthreads();

    for (int ch = 0; ch < 5; ch++) {
        int ks = q0 - 128 + ch * KC;
        if (ks + KC - 1 < 0 || ks >= Sdim) continue;

#pragma unroll
        for (int i = 0; i < 4; i++) {
            int idx = tid + 256 * i;
            int r = idx >> 4, c4 = (idx & 15) * 4;
            const float* base = qkv + ((size_t)(b * Sdim + ks + r)) * E3 + h * Dh + c4;
            *(float4*)(sK + r * PQ + c4) = *(const float4*)(base + Edim);
            *(float4*)(sV + r * PQ + c4) = *(const float4*)(base + 2 * Edim);
        }
        __syncthreads();

        float sc[4][4];
#pragma unroll
        for (int j = 0; j < 4; j++)
#pragma unroll
            for (int i = 0; i < 4; i++) sc[j][i] = 0.f;
        for (int kd = 0; kd < Dh; kd += 4) {
            float4 qv[4], kv[4];
#pragma unroll
            for (int j = 0; j < 4; j++) qv[j] = *(const float4*)(sQ + (qg * 4 + j) * PQ + kd);
#pragma unroll
            for (int i = 0; i < 4; i++) kv[i] = *(const float4*)(sK + (kg + 16 * i) * PQ + kd);
#pragma unroll
            for (int j = 0; j < 4; j++)
#pragma unroll
                for (int i = 0; i < 4; i++)
                    sc[j][i] += qv[j].x * kv[i].x + qv[j].y * kv[i].y
                              + qv[j].z * kv[i].z + qv[j].w * kv[i].w;
        }
#pragma unroll
        for (int j = 0; j < 4; j++) {
            int qq = q0 + qg * 4 + j;
#pragma unroll
            for (int i = 0; i < 4; i++) {
                int kk = ks + kg + 16 * i;
                float s = sc[j][i] * 0.125f;
                int d = qq - kk; if (d < 0) d = -d;
                sc[j][i] = (d <= 128) ? s : -1e9f;
            }
        }
        float rmax[4];
#pragma unroll
        for (int j = 0; j < 4; j++)
            rmax[j] = fmaxf(fmaxf(sc[j][0], sc[j][1]), fmaxf(sc[j][2], sc[j][3]));
#pragma unroll
        for (int o = 1; o < 16; o <<= 1)
#pragma unroll
            for (int j = 0; j < 4; j++)
                rmax[j] = fmaxf(rmax[j], __shfl_xor_sync(0xffffffffu, rmax[j], o));

        float fac[4], rsum[4], mnew[4];
#pragma unroll
        for (int j = 0; j < 4; j++) {
            float mo = s_m[qg * 4 + j];
            float mn = fmaxf(mo, rmax[j]);
            float sum = 0.f;
#pragma unroll
            for (int i = 0; i < 4; i++) {
                float p = __expf(sc[j][i] - mn);
                sS[(qg * 4 + j) * PS + kg + 16 * i] = p;
                sum += p;
            }
            rsum[j] = sum;
            fac[j]  = __expf(mo - mn);
            mnew[j] = mn;
        }
#pragma unroll
        for (int o = 1; o < 16; o <<= 1)
#pragma unroll
            for (int j = 0; j < 4; j++)
                rsum[j] += __shfl_xor_sync(0xffffffffu, rsum[j], o);
        if (kg == 0) {
#pragma unroll
            for (int j = 0; j < 4; j++) {
                int q = qg * 4 + j;
                s_m[q] = mnew[j];
                s_l[q] = s_l[q] * fac[j] + rsum[j];
                s_fac[q] = fac[j];
            }
        }
        __syncthreads();

        float f = s_fac[aq];
#pragma unroll
        for (int e = 0; e < 16; e++) acc[e] *= f;
        const float* vb = sV + ad;
        const float* pr = sS + aq * PS;
        for (int k = 0; k < KC; k++) {
            float p = pr[k];
            float4 v0 = *(const float4*)(vb + k * PQ);
            float4 v1 = *(const float4*)(vb + k * PQ + 4);
            float4 v2 = *(const float4*)(vb + k * PQ + 8);
            float4 v3 = *(const float4*)(vb + k * PQ + 12);
            acc[0]  += p * v0.x; acc[1]  += p * v0.y; acc[2]  += p * v0.z; acc[3]  += p * v0.w;
            acc[4]  += p * v1.x; acc[5]  += p * v1.y; acc[6]  += p * v1.z; acc[7]  += p * v1.w;
            acc[8]  += p * v2.x; acc[9]  += p * v2.y; acc[10] += p * v2.z; acc[11] += p * v2.w;
            acc[12] += p * v3.x; acc[13] += p * v3.y; acc[14] += p * v3.z; acc[15] += p * v3.w;
        }
        __syncthreads();
    }

    float invl = 1.f / s_l[aq];
    __half* op = out + ((size_t)(b * Sdim + q0 + aq)) * Edim + h * Dh + ad;
#pragma unroll
    for (int e = 0; e < 16; e += 2) {
        *(__half2*)(op + e) = __floats2half2_rn(acc[e] * invl, acc[e + 1] * invl);
    }
}

// =================== launch ================================================
extern "C" void kernel_launch(void* const* d_in, const int* in_sizes, int n_in,
                              void* d_out, int out_size) {
    const float* src    = (const float*)d_in[0];
    const float* Wqkv   = (const float*)d_in[1];
    const float* bqkv   = (const float*)d_in[2];
    const float* Wout   = (const float*)d_in[3];
    const float* bout   = (const float*)d_in[4];
    const float* gamma1 = (const float*)d_in[5];
    const float* beta1  = (const float*)d_in[6];
    const float* gamma2 = (const float*)d_in[7];
    const float* beta2  = (const float*)d_in[8];
    const float* Wg     = (const float*)d_in[9];
    const float* bg     = (const float*)d_in[10];
    const float* Wv     = (const float*)d_in[11];
    const float* bv     = (const float*)d_in[12];
    const float* Wo     = (const float*)d_in[13];
    const float* bo     = (const float*)d_in[14];
    float* out = (float*)d_out;

    float *p_qkv, *p_x1, *p_gate;
    __half *p_h, *p_h2, *p_attn, *p_act;
    __half *t_qkv, *t_out, *t_g, *t_v, *t_o;
    cudaGetSymbolAddress((void**)&p_qkv,  g_qkv);
    cudaGetSymbolAddress((void**)&p_x1,   g_x1);
    cudaGetSymbolAddress((void**)&p_gate, g_gate);
    cudaGetSymbolAddress((void**)&p_h,    g_h_h);
    cudaGetSymbolAddress((void**)&p_h2,   g_h2_h);
    cudaGetSymbolAddress((void**)&p_attn, g_attn_h);
    cudaGetSymbolAddress((void**)&p_act,  g_act_h);
    cudaGetSymbolAddress((void**)&t_qkv,  g_Wt_qkv);
    cudaGetSymbolAddress((void**)&t_out,  g_Wt_out);
    cudaGetSymbolAddress((void**)&t_g,    g_Wt_g);
    cudaGetSymbolAddress((void**)&t_v,    g_Wt_v);
    cudaGetSymbolAddress((void**)&t_o,    g_Wt_o);

    cudaFuncSetAttribute(gemm_h<0, float>,  cudaFuncAttributeMaxDynamicSharedMemorySize, GSMEM);
    cudaFuncSetAttribute(gemm_h<1, float>,  cudaFuncAttributeMaxDynamicSharedMemorySize, GSMEM);
    cudaFuncSetAttribute(gemm_h<2, __half>, cudaFuncAttributeMaxDynamicSharedMemorySize, GSMEM);
    cudaFuncSetAttribute(fattn_kernel, cudaFuncAttributeMaxDynamicSharedMemorySize, ATT_SMEM);

    dim3 tb(32, 8);
    transpose_h_kernel<<<dim3(E3 / 32,  Edim / 32), tb>>>(Wqkv, t_qkv, Edim, E3);
    transpose_h_kernel<<<dim3(Edim / 32, Edim / 32), tb>>>(Wout, t_out, Edim, Edim);
    transpose_h_kernel<<<dim3(FFd / 32,  Edim / 32), tb>>>(Wg,   t_g,   Edim, FFd);
    transpose_h_kernel<<<dim3(FFd / 32,  Edim / 32), tb>>>(Wv,   t_v,   Edim, FFd);
    transpose_h_kernel<<<dim3(Edim / 32, FFd / 32),  tb>>>(Wo,   t_o,   FFd,  Edim);

    // 1) LN1 -> half
    ln_kernel<<<NTOK, 256>>>(src, gamma1, beta1, p_h);
    // 2) QKV GEMM (half x half -> f32)
    gemm_h<0, float><<<dim3(E3 / 128, NTOK / 128), 256, GSMEM>>>(
        p_h, t_qkv, bqkv, nullptr, p_qkv, NTOK, E3, Edim);
    // 3) RoPE (f32)
    rope_kernel<<<NTOK, 512>>>(p_qkv);
    // 4) flash attention -> half
    fattn_kernel<<<dim3(Sdim / QT, Hdim, Bdim), 256, ATT_SMEM>>>(p_qkv, p_attn);
    // 5) out proj + residual -> x1 (f32)
    gemm_h<1, float><<<dim3(Edim / 128, NTOK / 128), 256, GSMEM>>>(
        p_attn, t_out, bout, src, p_x1, NTOK, Edim, Edim);
    // 6) LN2 -> half
    ln_kernel<<<NTOK, 256>>>(p_x1, gamma2, beta2, p_h2);
    // 7) gate = h2 @ Wg + bg (f32, needed for gelu aux)
    gemm_h<0, float><<<dim3(FFd / 128, NTOK / 128), 256, GSMEM>>>(
        p_h2, t_g, bg, nullptr, p_gate, NTOK, FFd, Edim);
    // 8) act = gelu(gate) * (h2 @ Wv + bv) -> half
    gemm_h<2, __half><<<dim3(FFd / 128, NTOK / 128), 256, GSMEM>>>(
        p_h2, t_v, bv, p_gate, p_act, NTOK, FFd, Edim);
    // 9) out = x1 + act @ Wo + bo (f32)
    gemm_h<1, float><<<dim3(Edim / 128, NTOK / 128), 256, GSMEM>>>(
        p_act, t_o, bo, p_x1, out, NTOK, Edim, FFd);
}

// round 15
// speedup vs baseline: 7.0010x; 1.6266x over previous
#include <cuda_runtime.h>
#include <cuda_fp16.h>
#include <stdint.h>
#include <math.h>

#define Bdim 4
#define Sdim 2048
#define Edim 1024
#define Hdim 16
#define Dh   64
#define FFd  4096
#define NTOK (Bdim*Sdim)      // 8192
#define E3   (3*Edim)         // 3072
#define LNEPS 1e-5f

// ---------------- scratch (static device memory, no allocs) ----------------
__device__ __half g_qkv [NTOK*(size_t)E3];     // half qkv (post-GEMM, post-RoPE)
__device__ float  g_x1  [NTOK*(size_t)Edim];   // residual 1 (f32)
__device__ float  g_gate[NTOK*(size_t)FFd];    // gate (f32, gelu aux)
__device__ __half g_h_h   [NTOK*(size_t)Edim]; // ln1 out
__device__ __half g_h2_h  [NTOK*(size_t)Edim]; // ln2 out
__device__ __half g_attn_h[NTOK*(size_t)Edim]; // attention out
__device__ __half g_act_h [NTOK*(size_t)FFd];  // gelu(gate)*val
// transposed half weights  Wt[n][k] = W[k][n]
__device__ __half g_Wt_qkv[(size_t)E3  * Edim];
__device__ __half g_Wt_out[(size_t)Edim* Edim];
__device__ __half g_Wt_g  [(size_t)FFd * Edim];
__device__ __half g_Wt_v  [(size_t)FFd * Edim];
__device__ __half g_Wt_o  [(size_t)Edim* FFd];

// =================== small PTX helpers =====================================
__device__ __forceinline__ uint32_t smem_u32(const void* p) {
    uint32_t a;
    asm("{ .reg .u64 t; cvta.to.shared.u64 t, %1; cvt.u32.u64 %0, t; }"
        : "=r"(a) : "l"(p));
    return a;
}
__device__ __forceinline__ void cp_async16(uint32_t dst, const void* src) {
    asm volatile("cp.async.cg.shared.global [%0], [%1], 16;"
                 :: "r"(dst), "l"(src) : "memory");
}
__device__ __forceinline__ void cp_commit() {
    asm volatile("cp.async.commit_group;" ::: "memory");
}
template <int N>
__device__ __forceinline__ void cp_wait() {
    asm volatile("cp.async.wait_group %0;" :: "n"(N) : "memory");
}
__device__ __forceinline__ void mma_f16(float* c, const uint32_t* a,
                                        const uint32_t* b) {
    asm volatile(
        "mma.sync.aligned.m16n8k16.row.col.f32.f16.f16.f32 "
        "{%0,%1,%2,%3}, {%4,%5,%6,%7}, {%8,%9}, {%0,%1,%2,%3};"
        : "+f"(c[0]), "+f"(c[1]), "+f"(c[2]), "+f"(c[3])
        : "r"(a[0]), "r"(a[1]), "r"(a[2]), "r"(a[3]), "r"(b[0]), "r"(b[1]));
}

// =================== fp16 mma.sync GEMM ====================================
#define BKH 64
#define PH  72
#define ATILE (128 * PH)
#define GSMEM (4 * ATILE * 2)

template <int EPI, typename OutT>
__global__ void __launch_bounds__(256, 2)
gemm_h(const __half* __restrict__ A, const __half* __restrict__ Bt,
       const float* __restrict__ bias, const float* __restrict__ aux,
       OutT* __restrict__ C, int M, int N, int K) {
    extern __shared__ __half smh[];
    __half* sA = smh;
    __half* sB = smh + 2 * ATILE;

    const int tid  = threadIdx.x;
    const int wid  = tid >> 5;
    const int lane = tid & 31;
    const int wm   = wid >> 2;
    const int wn   = wid & 3;
    const int bm   = blockIdx.y * 128;
    const int bn   = blockIdx.x * 128;
    const int qr   = lane >> 2;
    const int qc   = lane & 3;

    const uint32_t sa_u = smem_u32(sA);
    const uint32_t sb_u = smem_u32(sB);
    const int KT = K / BKH;

    float acc[4][4][4];
#pragma unroll
    for (int i = 0; i < 4; i++)
#pragma unroll
        for (int j = 0; j < 4; j++)
#pragma unroll
            for (int e = 0; e < 4; e++) acc[i][j][e] = 0.f;

    {
        const __half* Ag = A  + (size_t)bm * K;
        const __half* Bg = Bt + (size_t)bn * K;
#pragma unroll
        for (int i = 0; i < 4; i++) {
            int idx = tid + 256 * i;
            int r = idx >> 3, c8 = (idx & 7) * 8;
            cp_async16(sa_u + (r * PH + c8) * 2, Ag + (size_t)r * K + c8);
            cp_async16(sb_u + (r * PH + c8) * 2, Bg + (size_t)r * K + c8);
        }
        cp_commit();
    }

    for (int kt = 0; kt < KT; kt++) {
        int buf = kt & 1;
        if (kt + 1 < KT) {
            int nb = (kt + 1) & 1;
            int k0 = (kt + 1) * BKH;
            const __half* Ag = A  + (size_t)bm * K + k0;
            const __half* Bg = Bt + (size_t)bn * K + k0;
            uint32_t sa_o = sa_u + nb * ATILE * 2;
            uint32_t sb_o = sb_u + nb * ATILE * 2;
#pragma unroll
            for (int i = 0; i < 4; i++) {
                int idx = tid + 256 * i;
                int r = idx >> 3, c8 = (idx & 7) * 8;
                cp_async16(sa_o + (r * PH + c8) * 2, Ag + (size_t)r * K + c8);
                cp_async16(sb_o + (r * PH + c8) * 2, Bg + (size_t)r * K + c8);
            }
        }
        cp_commit();
        cp_wait<1>();
        __syncthreads();

        const __half* aT = sA + buf * ATILE + (wm * 64) * PH;
        const __half* bT = sB + buf * ATILE + (wn * 32) * PH;

#pragma unroll
        for (int ks = 0; ks < 4; ks++) {
            int kb = ks * 16 + 2 * qc;
            uint32_t af[4][4], bf[4][2];
#pragma unroll
            for (int mt = 0; mt < 4; mt++) {
                int r = mt * 16 + qr;
                af[mt][0] = *(const uint32_t*)(aT + r * PH + kb);
                af[mt][1] = *(const uint32_t*)(aT + (r + 8) * PH + kb);
                af[mt][2] = *(const uint32_t*)(aT + r * PH + kb + 8);
                af[mt][3] = *(const uint32_t*)(aT + (r + 8) * PH + kb + 8);
            }
#pragma unroll
            for (int nt = 0; nt < 4; nt++) {
                int n = nt * 8 + qr;
                bf[nt][0] = *(const uint32_t*)(bT + n * PH + kb);
                bf[nt][1] = *(const uint32_t*)(bT + n * PH + kb + 8);
            }
#pragma unroll
            for (int mt = 0; mt < 4; mt++)
#pragma unroll
                for (int nt = 0; nt < 4; nt++)
                    mma_f16(acc[mt][nt], af[mt], bf[nt]);
        }
        __syncthreads();
    }

#pragma unroll
    for (int mt = 0; mt < 4; mt++) {
#pragma unroll
        for (int nt = 0; nt < 4; nt++) {
            int r1 = bm + wm * 64 + mt * 16 + qr;
            int r2 = r1 + 8;
            int c  = bn + wn * 32 + nt * 8 + 2 * qc;
            float b0 = bias[c], b1 = bias[c + 1];
            float o00 = acc[mt][nt][0] + b0;
            float o01 = acc[mt][nt][1] + b1;
            float o10 = acc[mt][nt][2] + b0;
            float o11 = acc[mt][nt][3] + b1;
            if (EPI == 1) {
                float2 x0 = *(const float2*)(aux + (size_t)r1 * N + c);
                float2 x1 = *(const float2*)(aux + (size_t)r2 * N + c);
                o00 += x0.x; o01 += x0.y; o10 += x1.x; o11 += x1.y;
            }
            if (EPI == 2) {
                const float kk = 0.7071067811865476f;
                float2 x0 = *(const float2*)(aux + (size_t)r1 * N + c);
                float2 x1 = *(const float2*)(aux + (size_t)r2 * N + c);
                o00 *= 0.5f * x0.x * (1.f + erff(x0.x * kk));
                o01 *= 0.5f * x0.y * (1.f + erff(x0.y * kk));
                o10 *= 0.5f * x1.x * (1.f + erff(x1.x * kk));
                o11 *= 0.5f * x1.y * (1.f + erff(x1.y * kk));
            }
            if (sizeof(OutT) == 4) {
                *(float2*)((float*)C + (size_t)r1 * N + c) = make_float2(o00, o01);
                *(float2*)((float*)C + (size_t)r2 * N + c) = make_float2(o10, o11);
            } else {
                *(__half2*)((__half*)C + (size_t)r1 * N + c) = __floats2half2_rn(o00, o01);
                *(__half2*)((__half*)C + (size_t)r2 * N + c) = __floats2half2_rn(o10, o11);
            }
        }
    }
}

// =================== weight transpose (f32 -> half) ========================
__global__ void transpose_h_kernel(const float* __restrict__ src,
                                   __half* __restrict__ dst, int R, int C) {
    __shared__ float t[32][33];
    int x = blockIdx.x * 32 + threadIdx.x;
#pragma unroll
    for (int j = 0; j < 32; j += 8) {
        int y = blockIdx.y * 32 + threadIdx.y + j;
        t[threadIdx.y + j][threadIdx.x] = src[(size_t)y * C + x];
    }
    __syncthreads();
    int ox = blockIdx.y * 32 + threadIdx.x;
#pragma unroll
    for (int j = 0; j < 32; j += 8) {
        int oy = blockIdx.x * 32 + threadIdx.y + j;
        dst[(size_t)oy * R + ox] = __float2half_rn(t[threadIdx.x][threadIdx.y + j]);
    }
}

// =================== layernorm (f32 in -> half out) ========================
__global__ void ln_kernel(const float* __restrict__ x,
                          const float* __restrict__ gamma,
                          const float* __restrict__ beta,
                          __half* __restrict__ out) {
    int n = blockIdx.x;
    int tid = threadIdx.x;
    const float* row = x + (size_t)n * Edim;
    __half* orow = out + (size_t)n * Edim;

    float v[4];
    float s = 0.f;
#pragma unroll
    for (int i = 0; i < 4; i++) { v[i] = row[tid + 256 * i]; s += v[i]; }

    __shared__ float sh[8];
    int lane = tid & 31, warp = tid >> 5;
#pragma unroll
    for (int o = 16; o; o >>= 1) s += __shfl_xor_sync(0xffffffffu, s, o);
    if (lane == 0) sh[warp] = s;
    __syncthreads();
    if (tid < 8) {
        float t = sh[tid];
#pragma unroll
        for (int o = 4; o; o >>= 1) t += __shfl_xor_sync(0xffu, t, o);
        if (tid == 0) sh[0] = t;
    }
    __syncthreads();
    float mu = sh[0] * (1.f / Edim);
    __syncthreads();

    float s2 = 0.f;
#pragma unroll
    for (int i = 0; i < 4; i++) { float d = v[i] - mu; s2 += d * d; }
#pragma unroll
    for (int o = 16; o; o >>= 1) s2 += __shfl_xor_sync(0xffffffffu, s2, o);
    if (lane == 0) sh[warp] = s2;
    __syncthreads();
    if (tid < 8) {
        float t = sh[tid];
#pragma unroll
        for (int o = 4; o; o >>= 1) t += __shfl_xor_sync(0xffu, t, o);
        if (tid == 0) sh[0] = t;
    }
    __syncthreads();
    float var = sh[0] * (1.f / Edim);
    float r = rsqrtf(var + LNEPS);

#pragma unroll
    for (int i = 0; i < 4; i++) {
        int c = tid + 256 * i;
        orow[c] = __float2half_rn((v[i] - mu) * r * gamma[c] + beta[c]);
    }
}

// =================== RoPE (half in/out, f32 math) ==========================
__global__ void rope_kernel(__half* __restrict__ qkv) {
    int n = blockIdx.x;
    int s = n & (Sdim - 1);
    int tid = threadIdx.x;
    int h = tid >> 5;
    int j = tid & 31;
    float inv = expf(-(float)(2 * j) * (1.f / 64.f) * 9.210340371976184f);
    float ang = (float)s * inv;
    float c, sn;
    sincosf(ang, &sn, &c);
#pragma unroll
    for (int cc = 0; cc < 2; cc++) {
        __half* p = qkv + (size_t)n * E3 + cc * Edim + h * Dh;
        float x1 = __half2float(p[j]);
        float x2 = __half2float(p[j + 32]);
        p[j]      = __float2half_rn(x1 * c - x2 * sn);
        p[j + 32] = __float2half_rn(x2 * c + x1 * sn);
    }
}

// =================== tensor-core flash attention ===========================
// CTA: 64 queries x (h,b). 128 threads = 4 warps, warp w owns rows [16w,16w+16).
// 5 chunks of 64 keys. S and O via m16n8k16 mma, online softmax on fragments.
#define PS2 72

__global__ void __launch_bounds__(128, 4)
fattn_kernel(const __half* __restrict__ qkv, __half* __restrict__ out) {
    __shared__ __half sQ [64 * PS2];
    __shared__ __half sK [64 * PS2];
    __shared__ __half sVt[64 * PS2];   // [d][key]
    __shared__ __half sP [64 * PS2];   // [q][key]

    const int tid  = threadIdx.x;
    const int w    = tid >> 5;
    const int lane = tid & 31;
    const int qr   = lane >> 2;
    const int qc   = lane & 3;
    const int q0   = blockIdx.x * 64;
    const int h    = blockIdx.y;
    const int b    = blockIdx.z;

    // load Q tile (64 rows x 64 halves = 128B rows)
#pragma unroll
    for (int i = 0; i < 4; i++) {
        int idx = tid + 128 * i;
        int r = idx >> 3, c8 = (idx & 7) * 8;
        *(uint4*)(sQ + r * PS2 + c8) =
            *(const uint4*)(qkv + ((size_t)(b * Sdim + q0 + r)) * E3 + h * Dh + c8);
    }

    float mA = -1e30f, lA = 0.f, mB = -1e30f, lB = 0.f;
    float oacc[8][4];
#pragma unroll
    for (int nt = 0; nt < 8; nt++)
#pragma unroll
        for (int e = 0; e < 4; e++) oacc[nt][e] = 0.f;

    const int rowA = w * 16 + qr;       // local q row (A half of fragment)
    __syncthreads();

    for (int ch = 0; ch < 5; ch++) {
        int ks = q0 - 128 + ch * 64;
        if (ks + 63 < 0 || ks >= Sdim) continue;

        // load K (row=key) and V transposed (row=d)
#pragma unroll
        for (int i = 0; i < 4; i++) {
            int idx = tid + 128 * i;
            int r = idx >> 3, c8 = (idx & 7) * 8;
            const __half* base = qkv + ((size_t)(b * Sdim + ks + r)) * E3 + h * Dh + c8;
            *(uint4*)(sK + r * PS2 + c8) = *(const uint4*)(base + Edim);
            uint4 v = *(const uint4*)(base + 2 * Edim);
            const __half* vh = (const __half*)&v;
#pragma unroll
            for (int j = 0; j < 8; j++) sVt[(c8 + j) * PS2 + r] = vh[j];
        }
        __syncthreads();

        // ---- S = Q @ K^T (warp: 16 q x 64 k)
        float c[8][4];
#pragma unroll
        for (int nt = 0; nt < 8; nt++)
#pragma unroll
            for (int e = 0; e < 4; e++) c[nt][e] = 0.f;
        const __half* qT = sQ + (w * 16) * PS2;
#pragma unroll
        for (int ks4 = 0; ks4 < 4; ks4++) {
            int kb = ks4 * 16 + 2 * qc;
            uint32_t af[4];
            af[0] = *(const uint32_t*)(qT + qr * PS2 + kb);
            af[1] = *(const uint32_t*)(qT + (qr + 8) * PS2 + kb);
            af[2] = *(const uint32_t*)(qT + qr * PS2 + kb + 8);
            af[3] = *(const uint32_t*)(qT + (qr + 8) * PS2 + kb + 8);
#pragma unroll
            for (int nt = 0; nt < 8; nt++) {
                uint32_t bf[2];
                bf[0] = *(const uint32_t*)(sK + (nt * 8 + qr) * PS2 + kb);
                bf[1] = *(const uint32_t*)(sK + (nt * 8 + qr) * PS2 + kb + 8);
                mma_f16(c[nt], af, bf);
            }
        }

        // ---- scale + window mask
        int gqA = q0 + rowA, gqB = gqA + 8;
#pragma unroll
        for (int nt = 0; nt < 8; nt++) {
            int k0c = ks + nt * 8 + 2 * qc;
#pragma unroll
            for (int e = 0; e < 4; e++) {
                int gk = k0c + (e & 1);
                int gq = (e < 2) ? gqA : gqB;
                int d = gq - gk; if (d < 0) d = -d;
                c[nt][e] = (d <= 128) ? c[nt][e] * 0.125f : -1e9f;
            }
        }

        // ---- row max (quad reduction over lanes qc)
        float rA = -1e30f, rB = -1e30f;
#pragma unroll
        for (int nt = 0; nt < 8; nt++) {
            rA = fmaxf(rA, fmaxf(c[nt][0], c[nt][1]));
            rB = fmaxf(rB, fmaxf(c[nt][2], c[nt][3]));
        }
        rA = fmaxf(rA, __shfl_xor_sync(0xffffffffu, rA, 1));
        rA = fmaxf(rA, __shfl_xor_sync(0xffffffffu, rA, 2));
        rB = fmaxf(rB, __shfl_xor_sync(0xffffffffu, rB, 1));
        rB = fmaxf(rB, __shfl_xor_sync(0xffffffffu, rB, 2));

        float mnA = fmaxf(mA, rA), mnB = fmaxf(mB, rB);
        float facA = __expf(mA - mnA), facB = __expf(mB - mnB);
        mA = mnA; mB = mnB;

        // ---- P = exp(S - m), store to sP (own rows only), row sums
        float sAcc = 0.f, sBcc = 0.f;
        __half* pA = sP + rowA * PS2;
        __half* pB = sP + (rowA + 8) * PS2;
#pragma unroll
        for (int nt = 0; nt < 8; nt++) {
            int colc = nt * 8 + 2 * qc;
            float p0 = __expf(c[nt][0] - mA);
            float p1 = __expf(c[nt][1] - mA);
            float p2 = __expf(c[nt][2] - mB);
            float p3 = __expf(c[nt][3] - mB);
            sAcc += p0 + p1; sBcc += p2 + p3;
            *(__half2*)(pA + colc) = __floats2half2_rn(p0, p1);
            *(__half2*)(pB + colc) = __floats2half2_rn(p2, p3);
        }
        sAcc += __shfl_xor_sync(0xffffffffu, sAcc, 1);
        sAcc += __shfl_xor_sync(0xffffffffu, sAcc, 2);
        sBcc += __shfl_xor_sync(0xffffffffu, sBcc, 1);
        sBcc += __shfl_xor_sync(0xffffffffu, sBcc, 2);
        lA = lA * facA + sAcc;
        lB = lB * facB + sBcc;

        // ---- rescale O accumulators
#pragma unroll
        for (int nt = 0; nt < 8; nt++) {
            oacc[nt][0] *= facA; oacc[nt][1] *= facA;
            oacc[nt][2] *= facB; oacc[nt][3] *= facB;
        }

        // ---- O += P @ V  (A = sP rows, Bt = sVt[d][key])
        const __half* pT = sP + (w * 16) * PS2;
#pragma unroll
        for (int ks4 = 0; ks4 < 4; ks4++) {
            int kb = ks4 * 16 + 2 * qc;
            uint32_t af[4];
            af[0] = *(const uint32_t*)(pT + qr * PS2 + kb);
            af[1] = *(const uint32_t*)(pT + (qr + 8) * PS2 + kb);
            af[2] = *(const uint32_t*)(pT + qr * PS2 + kb + 8);
            af[3] = *(const uint32_t*)(pT + (qr + 8) * PS2 + kb + 8);
#pragma unroll
            for (int nt = 0; nt < 8; nt++) {
                uint32_t bf[2];
                bf[0] = *(const uint32_t*)(sVt + (nt * 8 + qr) * PS2 + kb);
                bf[1] = *(const uint32_t*)(sVt + (nt * 8 + qr) * PS2 + kb + 8);
                mma_f16(oacc[nt], af, bf);
            }
        }
        __syncthreads();   // protect sK/sVt before next chunk's loads
    }

    // ---- normalize + store (half)
    float invA = 1.f / lA, invB = 1.f / lB;
    int gqA = q0 + rowA;
    __half* oA = out + ((size_t)(b * Sdim + gqA)) * Edim + h * Dh;
    __half* oB = oA + (size_t)8 * Edim;
#pragma unroll
    for (int nt = 0; nt < 8; nt++) {
        int col = nt * 8 + 2 * qc;
        *(__half2*)(oA + col) = __floats2half2_rn(oacc[nt][0] * invA, oacc[nt][1] * invA);
        *(__half2*)(oB + col) = __floats2half2_rn(oacc[nt][2] * invB, oacc[nt][3] * invB);
    }
}

// =================== launch ================================================
extern "C" void kernel_launch(void* const* d_in, const int* in_sizes, int n_in,
                              void* d_out, int out_size) {
    const float* src    = (const float*)d_in[0];
    const float* Wqkv   = (const float*)d_in[1];
    const float* bqkv   = (const float*)d_in[2];
    const float* Wout   = (const float*)d_in[3];
    const float* bout   = (const float*)d_in[4];
    const float* gamma1 = (const float*)d_in[5];
    const float* beta1  = (const float*)d_in[6];
    const float* gamma2 = (const float*)d_in[7];
    const float* beta2  = (const float*)d_in[8];
    const float* Wg     = (const float*)d_in[9];
    const float* bg     = (const float*)d_in[10];
    const float* Wv     = (const float*)d_in[11];
    const float* bv     = (const float*)d_in[12];
    const float* Wo     = (const float*)d_in[13];
    const float* bo     = (const float*)d_in[14];
    float* out = (float*)d_out;

    float *p_x1, *p_gate;
    __half *p_qkv, *p_h, *p_h2, *p_attn, *p_act;
    __half *t_qkv, *t_out, *t_g, *t_v, *t_o;
    cudaGetSymbolAddress((void**)&p_qkv,  g_qkv);
    cudaGetSymbolAddress((void**)&p_x1,   g_x1);
    cudaGetSymbolAddress((void**)&p_gate, g_gate);
    cudaGetSymbolAddress((void**)&p_h,    g_h_h);
    cudaGetSymbolAddress((void**)&p_h2,   g_h2_h);
    cudaGetSymbolAddress((void**)&p_attn, g_attn_h);
    cudaGetSymbolAddress((void**)&p_act,  g_act_h);
    cudaGetSymbolAddress((void**)&t_qkv,  g_Wt_qkv);
    cudaGetSymbolAddress((void**)&t_out,  g_Wt_out);
    cudaGetSymbolAddress((void**)&t_g,    g_Wt_g);
    cudaGetSymbolAddress((void**)&t_v,    g_Wt_v);
    cudaGetSymbolAddress((void**)&t_o,    g_Wt_o);

    cudaFuncSetAttribute(gemm_h<0, __half>, cudaFuncAttributeMaxDynamicSharedMemorySize, GSMEM);
    cudaFuncSetAttribute(gemm_h<0, float>,  cudaFuncAttributeMaxDynamicSharedMemorySize, GSMEM);
    cudaFuncSetAttribute(gemm_h<1, float>,  cudaFuncAttributeMaxDynamicSharedMemorySize, GSMEM);
    cudaFuncSetAttribute(gemm_h<2, __half>, cudaFuncAttributeMaxDynamicSharedMemorySize, GSMEM);

    dim3 tb(32, 8);
    transpose_h_kernel<<<dim3(E3 / 32,  Edim / 32), tb>>>(Wqkv, t_qkv, Edim, E3);
    transpose_h_kernel<<<dim3(Edim / 32, Edim / 32), tb>>>(Wout, t_out, Edim, Edim);
    transpose_h_kernel<<<dim3(FFd / 32,  Edim / 32), tb>>>(Wg,   t_g,   Edim, FFd);
    transpose_h_kernel<<<dim3(FFd / 32,  Edim / 32), tb>>>(Wv,   t_v,   Edim, FFd);
    transpose_h_kernel<<<dim3(Edim / 32, FFd / 32),  tb>>>(Wo,   t_o,   FFd,  Edim);

    // 1) LN1 -> half
    ln_kernel<<<NTOK, 256>>>(src, gamma1, beta1, p_h);
    // 2) QKV GEMM -> half qkv
    gemm_h<0, __half><<<dim3(E3 / 128, NTOK / 128), 256, GSMEM>>>(
        p_h, t_qkv, bqkv, nullptr, p_qkv, NTOK, E3, Edim);
    // 3) RoPE (half)
    rope_kernel<<<NTOK, 512>>>(p_qkv);
    // 4) tensor-core flash attention -> half
    fattn_kernel<<<dim3(Sdim / 64, Hdim, Bdim), 128>>>(p_qkv, p_attn);
    // 5) out proj + residual -> x1 (f32)
    gemm_h<1, float><<<dim3(Edim / 128, NTOK / 128), 256, GSMEM>>>(
        p_attn, t_out, bout, src, p_x1, NTOK, Edim, Edim);
    // 6) LN2 -> half
    ln_kernel<<<NTOK, 256>>>(p_x1, gamma2, beta2, p_h2);
    // 7) gate = h2 @ Wg + bg (f32, gelu aux)
    gemm_h<0, float><<<dim3(FFd / 128, NTOK / 128), 256, GSMEM>>>(
        p_h2, t_g, bg, nullptr, p_gate, NTOK, FFd, Edim);
    // 8) act = gelu(gate) * (h2 @ Wv + bv) -> half
    gemm_h<2, __half><<<dim3(FFd / 128, NTOK / 128), 256, GSMEM>>>(
        p_h2, t_v, bv, p_gate, p_act, NTOK, FFd, Edim);
    // 9) out = x1 + act @ Wo + bo (f32)
    gemm_h<1, float><<<dim3(Edim / 128, NTOK / 128), 256, GSMEM>>>(
        p_act, t_o, bo, p_x1, out, NTOK, Edim, FFd);
}

// round 16
// speedup vs baseline: 7.2905x; 1.0414x over previous
#include <cuda_runtime.h>
#include <cuda_fp16.h>
#include <stdint.h>
#include <math.h>

#define Bdim 4
#define Sdim 2048
#define Edim 1024
#define Hdim 16
#define Dh   64
#define FFd  4096
#define NTOK (Bdim*Sdim)      // 8192
#define E3   (3*Edim)         // 3072
#define LNEPS 1e-5f

// ---------------- scratch (static device memory, no allocs) ----------------
__device__ __half g_qkv [NTOK*(size_t)E3];     // half qkv (post-GEMM, post-RoPE)
__device__ float  g_x1  [NTOK*(size_t)Edim];   // residual 1 (f32)
__device__ __half g_gate_h[NTOK*(size_t)FFd];  // gate (half, gelu aux)
__device__ __half g_h_h   [NTOK*(size_t)Edim]; // ln1 out
__device__ __half g_h2_h  [NTOK*(size_t)Edim]; // ln2 out
__device__ __half g_attn_h[NTOK*(size_t)Edim]; // attention out
__device__ __half g_act_h [NTOK*(size_t)FFd];  // gelu(gate)*val
// transposed half weights  Wt[n][k] = W[k][n]
__device__ __half g_Wt_qkv[(size_t)E3  * Edim];
__device__ __half g_Wt_out[(size_t)Edim* Edim];
__device__ __half g_Wt_g  [(size_t)FFd * Edim];
__device__ __half g_Wt_v  [(size_t)FFd * Edim];
__device__ __half g_Wt_o  [(size_t)Edim* FFd];

// =================== small PTX helpers =====================================
__device__ __forceinline__ uint32_t smem_u32(const void* p) {
    uint32_t a;
    asm("{ .reg .u64 t; cvta.to.shared.u64 t, %1; cvt.u32.u64 %0, t; }"
        : "=r"(a) : "l"(p));
    return a;
}
__device__ __forceinline__ void cp_async16(uint32_t dst, const void* src) {
    asm volatile("cp.async.cg.shared.global [%0], [%1], 16;"
                 :: "r"(dst), "l"(src) : "memory");
}
__device__ __forceinline__ void cp_commit() {
    asm volatile("cp.async.commit_group;" ::: "memory");
}
template <int N>
__device__ __forceinline__ void cp_wait() {
    asm volatile("cp.async.wait_group %0;" :: "n"(N) : "memory");
}
__device__ __forceinline__ void mma_f16(float* c, const uint32_t* a,
                                        const uint32_t* b) {
    asm volatile(
        "mma.sync.aligned.m16n8k16.row.col.f32.f16.f16.f32 "
        "{%0,%1,%2,%3}, {%4,%5,%6,%7}, {%8,%9}, {%0,%1,%2,%3};"
        : "+f"(c[0]), "+f"(c[1]), "+f"(c[2]), "+f"(c[3])
        : "r"(a[0]), "r"(a[1]), "r"(a[2]), "r"(a[3]), "r"(b[0]), "r"(b[1]));
}
__device__ __forceinline__ void ldsm_x2_trans(uint32_t& r0, uint32_t& r1,
                                              uint32_t addr) {
    asm volatile("ldmatrix.sync.aligned.m8n8.x2.trans.shared.b16 {%0,%1}, [%2];"
                 : "=r"(r0), "=r"(r1) : "r"(addr));
}

// =================== fp16 mma.sync GEMM ====================================
#define BKH 64
#define PH  72
#define ATILE (128 * PH)
#define GSMEM (4 * ATILE * 2)

template <int EPI, typename OutT>
__global__ void __launch_bounds__(256, 2)
gemm_h(const __half* __restrict__ A, const __half* __restrict__ Bt,
       const float* __restrict__ bias, const void* __restrict__ aux,
       OutT* __restrict__ C, int M, int N, int K) {
    extern __shared__ __half smh[];
    __half* sA = smh;
    __half* sB = smh + 2 * ATILE;

    const int tid  = threadIdx.x;
    const int wid  = tid >> 5;
    const int lane = tid & 31;
    const int wm   = wid >> 2;
    const int wn   = wid & 3;
    const int bm   = blockIdx.y * 128;
    const int bn   = blockIdx.x * 128;
    const int qr   = lane >> 2;
    const int qc   = lane & 3;

    const uint32_t sa_u = smem_u32(sA);
    const uint32_t sb_u = smem_u32(sB);
    const int KT = K / BKH;

    float acc[4][4][4];
#pragma unroll
    for (int i = 0; i < 4; i++)
#pragma unroll
        for (int j = 0; j < 4; j++)
#pragma unroll
            for (int e = 0; e < 4; e++) acc[i][j][e] = 0.f;

    {
        const __half* Ag = A  + (size_t)bm * K;
        const __half* Bg = Bt + (size_t)bn * K;
#pragma unroll
        for (int i = 0; i < 4; i++) {
            int idx = tid + 256 * i;
            int r = idx >> 3, c8 = (idx & 7) * 8;
            cp_async16(sa_u + (r * PH + c8) * 2, Ag + (size_t)r * K + c8);
            cp_async16(sb_u + (r * PH + c8) * 2, Bg + (size_t)r * K + c8);
        }
        cp_commit();
    }

    for (int kt = 0; kt < KT; kt++) {
        int buf = kt & 1;
        if (kt + 1 < KT) {
            int nb = (kt + 1) & 1;
            int k0 = (kt + 1) * BKH;
            const __half* Ag = A  + (size_t)bm * K + k0;
            const __half* Bg = Bt + (size_t)bn * K + k0;
            uint32_t sa_o = sa_u + nb * ATILE * 2;
            uint32_t sb_o = sb_u + nb * ATILE * 2;
#pragma unroll
            for (int i = 0; i < 4; i++) {
                int idx = tid + 256 * i;
                int r = idx >> 3, c8 = (idx & 7) * 8;
                cp_async16(sa_o + (r * PH + c8) * 2, Ag + (size_t)r * K + c8);
                cp_async16(sb_o + (r * PH + c8) * 2, Bg + (size_t)r * K + c8);
            }
        }
        cp_commit();
        cp_wait<1>();
        __syncthreads();

        const __half* aT = sA + buf * ATILE + (wm * 64) * PH;
        const __half* bT = sB + buf * ATILE + (wn * 32) * PH;

#pragma unroll
        for (int ks = 0; ks < 4; ks++) {
            int kb = ks * 16 + 2 * qc;
            uint32_t af[4][4], bf[4][2];
#pragma unroll
            for (int mt = 0; mt < 4; mt++) {
                int r = mt * 16 + qr;
                af[mt][0] = *(const uint32_t*)(aT + r * PH + kb);
                af[mt][1] = *(const uint32_t*)(aT + (r + 8) * PH + kb);
                af[mt][2] = *(const uint32_t*)(aT + r * PH + kb + 8);
                af[mt][3] = *(const uint32_t*)(aT + (r + 8) * PH + kb + 8);
            }
#pragma unroll
            for (int nt = 0; nt < 4; nt++) {
                int n = nt * 8 + qr;
                bf[nt][0] = *(const uint32_t*)(bT + n * PH + kb);
                bf[nt][1] = *(const uint32_t*)(bT + n * PH + kb + 8);
            }
#pragma unroll
            for (int mt = 0; mt < 4; mt++)
#pragma unroll
                for (int nt = 0; nt < 4; nt++)
                    mma_f16(acc[mt][nt], af[mt], bf[nt]);
        }
        __syncthreads();
    }

#pragma unroll
    for (int mt = 0; mt < 4; mt++) {
#pragma unroll
        for (int nt = 0; nt < 4; nt++) {
            int r1 = bm + wm * 64 + mt * 16 + qr;
            int r2 = r1 + 8;
            int c  = bn + wn * 32 + nt * 8 + 2 * qc;
            float b0 = bias[c], b1 = bias[c + 1];
            float o00 = acc[mt][nt][0] + b0;
            float o01 = acc[mt][nt][1] + b1;
            float o10 = acc[mt][nt][2] + b0;
            float o11 = acc[mt][nt][3] + b1;
            if (EPI == 1) {   // residual add (f32 aux)
                const float* af32 = (const float*)aux;
                float2 x0 = *(const float2*)(af32 + (size_t)r1 * N + c);
                float2 x1 = *(const float2*)(af32 + (size_t)r2 * N + c);
                o00 += x0.x; o01 += x0.y; o10 += x1.x; o11 += x1.y;
            }
            if (EPI == 2) {   // gelu(gate half aux) * acc
                const __half* ah = (const __half*)aux;
                const float kk = 0.7071067811865476f;
                __half2 g0 = *(const __half2*)(ah + (size_t)r1 * N + c);
                __half2 g1 = *(const __half2*)(ah + (size_t)r2 * N + c);
                float gx = __half2float(g0.x), gy = __half2float(g0.y);
                float gz = __half2float(g1.x), gw = __half2float(g1.y);
                o00 *= 0.5f * gx * (1.f + erff(gx * kk));
                o01 *= 0.5f * gy * (1.f + erff(gy * kk));
                o10 *= 0.5f * gz * (1.f + erff(gz * kk));
                o11 *= 0.5f * gw * (1.f + erff(gw * kk));
            }
            if (sizeof(OutT) == 4) {
                *(float2*)((float*)C + (size_t)r1 * N + c) = make_float2(o00, o01);
                *(float2*)((float*)C + (size_t)r2 * N + c) = make_float2(o10, o11);
            } else {
                *(__half2*)((__half*)C + (size_t)r1 * N + c) = __floats2half2_rn(o00, o01);
                *(__half2*)((__half*)C + (size_t)r2 * N + c) = __floats2half2_rn(o10, o11);
            }
        }
    }
}

// =================== weight transpose (f32 -> half) ========================
__global__ void transpose_h_kernel(const float* __restrict__ src,
                                   __half* __restrict__ dst, int R, int C) {
    __shared__ float t[32][33];
    int x = blockIdx.x * 32 + threadIdx.x;
#pragma unroll
    for (int j = 0; j < 32; j += 8) {
        int y = blockIdx.y * 32 + threadIdx.y + j;
        t[threadIdx.y + j][threadIdx.x] = src[(size_t)y * C + x];
    }
    __syncthreads();
    int ox = blockIdx.y * 32 + threadIdx.x;
#pragma unroll
    for (int j = 0; j < 32; j += 8) {
        int oy = blockIdx.x * 32 + threadIdx.y + j;
        dst[(size_t)oy * R + ox] = __float2half_rn(t[threadIdx.x][threadIdx.y + j]);
    }
}

// =================== layernorm (f32 in -> half out, vectorized) ============
__global__ void ln_kernel(const float* __restrict__ x,
                          const float* __restrict__ gamma,
                          const float* __restrict__ beta,
                          __half* __restrict__ out) {
    int n = blockIdx.x;
    int tid = threadIdx.x;
    float4 v = *(const float4*)(x + (size_t)n * Edim + 4 * tid);
    float s = v.x + v.y + v.z + v.w;

    __shared__ float sh[8];
    int lane = tid & 31, warp = tid >> 5;
#pragma unroll
    for (int o = 16; o; o >>= 1) s += __shfl_xor_sync(0xffffffffu, s, o);
    if (lane == 0) sh[warp] = s;
    __syncthreads();
    if (tid < 8) {
        float t = sh[tid];
#pragma unroll
        for (int o = 4; o; o >>= 1) t += __shfl_xor_sync(0xffu, t, o);
        if (tid == 0) sh[0] = t;
    }
    __syncthreads();
    float mu = sh[0] * (1.f / Edim);
    __syncthreads();

    float dx = v.x - mu, dy = v.y - mu, dz = v.z - mu, dw = v.w - mu;
    float s2 = dx * dx + dy * dy + dz * dz + dw * dw;
#pragma unroll
    for (int o = 16; o; o >>= 1) s2 += __shfl_xor_sync(0xffffffffu, s2, o);
    if (lane == 0) sh[warp] = s2;
    __syncthreads();
    if (tid < 8) {
        float t = sh[tid];
#pragma unroll
        for (int o = 4; o; o >>= 1) t += __shfl_xor_sync(0xffu, t, o);
        if (tid == 0) sh[0] = t;
    }
    __syncthreads();
    float r = rsqrtf(sh[0] * (1.f / Edim) + LNEPS);

    float4 gm = *(const float4*)(gamma + 4 * tid);
    float4 bt = *(const float4*)(beta + 4 * tid);
    __half2 h0 = __floats2half2_rn(dx * r * gm.x + bt.x, dy * r * gm.y + bt.y);
    __half2 h1 = __floats2half2_rn(dz * r * gm.z + bt.z, dw * r * gm.w + bt.w);
    uint2 pk; pk.x = *(uint32_t*)&h0; pk.y = *(uint32_t*)&h1;
    *(uint2*)(out + (size_t)n * Edim + 4 * tid) = pk;
}

// =================== RoPE (half2 vectorized) ===============================
// block 256 = 16 heads x 16 j-pairs; grid NTOK
__global__ void rope_kernel(__half* __restrict__ qkv) {
    int n = blockIdx.x;
    int s = n & (Sdim - 1);
    int tid = threadIdx.x;
    int h  = tid >> 4;
    int jp = (tid & 15) * 2;          // j, j+1
    const float LG = 9.210340371976184f / 64.f;   // ln(10000)/64
    float i0 = expf(-(float)(2 * jp) * LG);
    float i1 = expf(-(float)(2 * (jp + 1)) * LG);
    float c0, s0, c1, s1;
    sincosf((float)s * i0, &s0, &c0);
    sincosf((float)s * i1, &s1, &c1);
#pragma unroll
    for (int cc = 0; cc < 2; cc++) {
        __half2* p = (__half2*)(qkv + (size_t)n * E3 + cc * Edim + h * Dh);
        __half2 a = p[jp >> 1];
        __half2 b = p[(jp >> 1) + 16];
        float ax = __half2float(a.x), ay = __half2float(a.y);
        float bx = __half2float(b.x), by = __half2float(b.y);
        p[jp >> 1]        = __floats2half2_rn(ax * c0 - bx * s0, ay * c1 - by * s1);
        p[(jp >> 1) + 16] = __floats2half2_rn(bx * c0 + ax * s0, by * c1 + ay * s1);
    }
}

// =================== tensor-core flash attention ===========================
// CTA: 64 queries x (h,b). 128 threads = 4 warps. V kept row-major; PV B-frags
// via ldmatrix.x2.trans (no transpose stores, no bank conflicts).
#define PS2 72

__global__ void __launch_bounds__(128, 4)
fattn_kernel(const __half* __restrict__ qkv, __half* __restrict__ out) {
    __shared__ __half sQ[64 * PS2];
    __shared__ __half sK[64 * PS2];
    __shared__ __half sV[64 * PS2];   // [key][d] row-major
    __shared__ __half sP[64 * PS2];   // [q][key]

    const int tid  = threadIdx.x;
    const int w    = tid >> 5;
    const int lane = tid & 31;
    const int qr   = lane >> 2;
    const int qc   = lane & 3;
    const int q0   = blockIdx.x * 64;
    const int h    = blockIdx.y;
    const int b    = blockIdx.z;

#pragma unroll
    for (int i = 0; i < 4; i++) {
        int idx = tid + 128 * i;
        int r = idx >> 3, c8 = (idx & 7) * 8;
        *(uint4*)(sQ + r * PS2 + c8) =
            *(const uint4*)(qkv + ((size_t)(b * Sdim + q0 + r)) * E3 + h * Dh + c8);
    }

    float mA = -1e30f, lA = 0.f, mB = -1e30f, lB = 0.f;
    float oacc[8][4];
#pragma unroll
    for (int nt = 0; nt < 8; nt++)
#pragma unroll
        for (int e = 0; e < 4; e++) oacc[nt][e] = 0.f;

    const int rowA = w * 16 + qr;
    const uint32_t sv_lane = smem_u32(sV) + (uint32_t)(((lane & 15) * PS2) * 2);
    __syncthreads();

    for (int ch = 0; ch < 5; ch++) {
        int ks = q0 - 128 + ch * 64;
        if (ks + 63 < 0 || ks >= Sdim) continue;

#pragma unroll
        for (int i = 0; i < 4; i++) {
            int idx = tid + 128 * i;
            int r = idx >> 3, c8 = (idx & 7) * 8;
            const __half* base = qkv + ((size_t)(b * Sdim + ks + r)) * E3 + h * Dh + c8;
            *(uint4*)(sK + r * PS2 + c8) = *(const uint4*)(base + Edim);
            *(uint4*)(sV + r * PS2 + c8) = *(const uint4*)(base + 2 * Edim);
        }
        __syncthreads();

        // ---- S = Q @ K^T
        float c[8][4];
#pragma unroll
        for (int nt = 0; nt < 8; nt++)
#pragma unroll
            for (int e = 0; e < 4; e++) c[nt][e] = 0.f;
        const __half* qT = sQ + (w * 16) * PS2;
#pragma unroll
        for (int ks4 = 0; ks4 < 4; ks4++) {
            int kb = ks4 * 16 + 2 * qc;
            uint32_t af[4];
            af[0] = *(const uint32_t*)(qT + qr * PS2 + kb);
            af[1] = *(const uint32_t*)(qT + (qr + 8) * PS2 + kb);
            af[2] = *(const uint32_t*)(qT + qr * PS2 + kb + 8);
            af[3] = *(const uint32_t*)(qT + (qr + 8) * PS2 + kb + 8);
#pragma unroll
            for (int nt = 0; nt < 8; nt++) {
                uint32_t bf[2];
                bf[0] = *(const uint32_t*)(sK + (nt * 8 + qr) * PS2 + kb);
                bf[1] = *(const uint32_t*)(sK + (nt * 8 + qr) * PS2 + kb + 8);
                mma_f16(c[nt], af, bf);
            }
        }

        // ---- scale + window mask
        int gqA = q0 + rowA, gqB = gqA + 8;
#pragma unroll
        for (int nt = 0; nt < 8; nt++) {
            int k0c = ks + nt * 8 + 2 * qc;
#pragma unroll
            for (int e = 0; e < 4; e++) {
                int gk = k0c + (e & 1);
                int gq = (e < 2) ? gqA : gqB;
                int d = gq - gk; if (d < 0) d = -d;
                c[nt][e] = (d <= 128) ? c[nt][e] * 0.125f : -1e9f;
            }
        }

        // ---- row max (quad reduce)
        float rA = -1e30f, rB = -1e30f;
#pragma unroll
        for (int nt = 0; nt < 8; nt++) {
            rA = fmaxf(rA, fmaxf(c[nt][0], c[nt][1]));
            rB = fmaxf(rB, fmaxf(c[nt][2], c[nt][3]));
        }
        rA = fmaxf(rA, __shfl_xor_sync(0xffffffffu, rA, 1));
        rA = fmaxf(rA, __shfl_xor_sync(0xffffffffu, rA, 2));
        rB = fmaxf(rB, __shfl_xor_sync(0xffffffffu, rB, 1));
        rB = fmaxf(rB, __shfl_xor_sync(0xffffffffu, rB, 2));

        float mnA = fmaxf(mA, rA), mnB = fmaxf(mB, rB);
        float facA = __expf(mA - mnA), facB = __expf(mB - mnB);
        mA = mnA; mB = mnB;

        // ---- P = exp(S - m) -> sP, row sums
        float sAcc = 0.f, sBcc = 0.f;
        __half* pA = sP + rowA * PS2;
        __half* pB = sP + (rowA + 8) * PS2;
#pragma unroll
        for (int nt = 0; nt < 8; nt++) {
            int colc = nt * 8 + 2 * qc;
            float p0 = __expf(c[nt][0] - mA);
            float p1 = __expf(c[nt][1] - mA);
            float p2 = __expf(c[nt][2] - mB);
            float p3 = __expf(c[nt][3] - mB);
            sAcc += p0 + p1; sBcc += p2 + p3;
            *(__half2*)(pA + colc) = __floats2half2_rn(p0, p1);
            *(__half2*)(pB + colc) = __floats2half2_rn(p2, p3);
        }
        sAcc += __shfl_xor_sync(0xffffffffu, sAcc, 1);
        sAcc += __shfl_xor_sync(0xffffffffu, sAcc, 2);
        sBcc += __shfl_xor_sync(0xffffffffu, sBcc, 1);
        sBcc += __shfl_xor_sync(0xffffffffu, sBcc, 2);
        lA = lA * facA + sAcc;
        lB = lB * facB + sBcc;

#pragma unroll
        for (int nt = 0; nt < 8; nt++) {
            oacc[nt][0] *= facA; oacc[nt][1] *= facA;
            oacc[nt][2] *= facB; oacc[nt][3] *= facB;
        }

        // ---- O += P @ V  (V row-major, B-frags via ldmatrix.trans)
        const __half* pT = sP + (w * 16) * PS2;
#pragma unroll
        for (int ks4 = 0; ks4 < 4; ks4++) {
            int kb = ks4 * 16 + 2 * qc;
            uint32_t af[4];
            af[0] = *(const uint32_t*)(pT + qr * PS2 + kb);
            af[1] = *(const uint32_t*)(pT + (qr + 8) * PS2 + kb);
            af[2] = *(const uint32_t*)(pT + qr * PS2 + kb + 8);
            af[3] = *(const uint32_t*)(pT + (qr + 8) * PS2 + kb + 8);
#pragma unroll
            for (int nt = 0; nt < 8; nt++) {
                uint32_t bf[2];
                ldsm_x2_trans(bf[0], bf[1],
                              sv_lane + (uint32_t)(((ks4 * 16) * PS2 + nt * 8) * 2));
                mma_f16(oacc[nt], af, bf);
            }
        }
        __syncthreads();
    }

    float invA = 1.f / lA, invB = 1.f / lB;
    int gqA = q0 + rowA;
    __half* oA = out + ((size_t)(b * Sdim + gqA)) * Edim + h * Dh;
    __half* oB = oA + (size_t)8 * Edim;
#pragma unroll
    for (int nt = 0; nt < 8; nt++) {
        int col = nt * 8 + 2 * qc;
        *(__half2*)(oA + col) = __floats2half2_rn(oacc[nt][0] * invA, oacc[nt][1] * invA);
        *(__half2*)(oB + col) = __floats2half2_rn(oacc[nt][2] * invB, oacc[nt][3] * invB);
    }
}

// =================== launch ================================================
extern "C" void kernel_launch(void* const* d_in, const int* in_sizes, int n_in,
                              void* d_out, int out_size) {
    const float* src    = (const float*)d_in[0];
    const float* Wqkv   = (const float*)d_in[1];
    const float* bqkv   = (const float*)d_in[2];
    const float* Wout   = (const float*)d_in[3];
    const float* bout   = (const float*)d_in[4];
    const float* gamma1 = (const float*)d_in[5];
    const float* beta1  = (const float*)d_in[6];
    const float* gamma2 = (const float*)d_in[7];
    const float* beta2  = (const float*)d_in[8];
    const float* Wg     = (const float*)d_in[9];
    const float* bg     = (const float*)d_in[10];
    const float* Wv     = (const float*)d_in[11];
    const float* bv     = (const float*)d_in[12];
    const float* Wo     = (const float*)d_in[13];
    const float* bo     = (const float*)d_in[14];
    float* out = (float*)d_out;

    float *p_x1;
    __half *p_qkv, *p_gate, *p_h, *p_h2, *p_attn, *p_act;
    __half *t_qkv, *t_out, *t_g, *t_v, *t_o;
    cudaGetSymbolAddress((void**)&p_qkv,  g_qkv);
    cudaGetSymbolAddress((void**)&p_x1,   g_x1);
    cudaGetSymbolAddress((void**)&p_gate, g_gate_h);
    cudaGetSymbolAddress((void**)&p_h,    g_h_h);
    cudaGetSymbolAddress((void**)&p_h2,   g_h2_h);
    cudaGetSymbolAddress((void**)&p_attn, g_attn_h);
    cudaGetSymbolAddress((void**)&p_act,  g_act_h);
    cudaGetSymbolAddress((void**)&t_qkv,  g_Wt_qkv);
    cudaGetSymbolAddress((void**)&t_out,  g_Wt_out);
    cudaGetSymbolAddress((void**)&t_g,    g_Wt_g);
    cudaGetSymbolAddress((void**)&t_v,    g_Wt_v);
    cudaGetSymbolAddress((void**)&t_o,    g_Wt_o);

    cudaFuncSetAttribute(gemm_h<0, __half>, cudaFuncAttributeMaxDynamicSharedMemorySize, GSMEM);
    cudaFuncSetAttribute(gemm_h<1, float>,  cudaFuncAttributeMaxDynamicSharedMemorySize, GSMEM);
    cudaFuncSetAttribute(gemm_h<2, __half>, cudaFuncAttributeMaxDynamicSharedMemorySize, GSMEM);

    dim3 tb(32, 8);
    transpose_h_kernel<<<dim3(E3 / 32,  Edim / 32), tb>>>(Wqkv, t_qkv, Edim, E3);
    transpose_h_kernel<<<dim3(Edim / 32, Edim / 32), tb>>>(Wout, t_out, Edim, Edim);
    transpose_h_kernel<<<dim3(FFd / 32,  Edim / 32), tb>>>(Wg,   t_g,   Edim, FFd);
    transpose_h_kernel<<<dim3(FFd / 32,  Edim / 32), tb>>>(Wv,   t_v,   Edim, FFd);
    transpose_h_kernel<<<dim3(Edim / 32, FFd / 32),  tb>>>(Wo,   t_o,   FFd,  Edim);

    // 1) LN1 -> half
    ln_kernel<<<NTOK, 256>>>(src, gamma1, beta1, p_h);
    // 2) QKV GEMM -> half qkv
    gemm_h<0, __half><<<dim3(E3 / 128, NTOK / 128), 256, GSMEM>>>(
        p_h, t_qkv, bqkv, nullptr, p_qkv, NTOK, E3, Edim);
    // 3) RoPE (half2)
    rope_kernel<<<NTOK, 256>>>(p_qkv);
    // 4) tensor-core flash attention -> half
    fattn_kernel<<<dim3(Sdim / 64, Hdim, Bdim), 128>>>(p_qkv, p_attn);
    // 5) out proj + residual -> x1 (f32)
    gemm_h<1, float><<<dim3(Edim / 128, NTOK / 128), 256, GSMEM>>>(
        p_attn, t_out, bout, src, p_x1, NTOK, Edim, Edim);
    // 6) LN2 -> half
    ln_kernel<<<NTOK, 256>>>(p_x1, gamma2, beta2, p_h2);
    // 7) gate = h2 @ Wg + bg -> half
    gemm_h<0, __half><<<dim3(FFd / 128, NTOK / 128), 256, GSMEM>>>(
        p_h2, t_g, bg, nullptr, p_gate, NTOK, FFd, Edim);
    // 8) act = gelu(gate) * (h2 @ Wv + bv) -> half
    gemm_h<2, __half><<<dim3(FFd / 128, NTOK / 128), 256, GSMEM>>>(
        p_h2, t_v, bv, p_gate, p_act, NTOK, FFd, Edim);
    // 9) out = x1 + act @ Wo + bo (f32)
    gemm_h<1, float><<<dim3(Edim / 128, NTOK / 128), 256, GSMEM>>>(
        p_act, t_o, bo, p_x1, out, NTOK, Edim, FFd);
}